// round 1
// baseline (speedup 1.0000x reference)
#include <cuda_runtime.h>
#include <math.h>

#define BB 8
#define SS 4096
#define TT (BB*SS)          // 32768 tokens
#define DD 1024
#define DKK 128
#define DVV 128
#define MM 256
#define EPSV 1e-6f

// ---------------- scratch (device globals; no allocation allowed) -------------
__device__ float g_q[(size_t)TT*DKK];
__device__ float g_k[(size_t)TT*DKK];
__device__ float g_v[(size_t)TT*DVV];
__device__ float g_pq[(size_t)TT*MM];   // later holds phi_q in place
__device__ float g_pk[(size_t)TT*MM];   // later holds phi_k in place
__device__ float g_qn[TT];
__device__ float g_kn[TT];
__device__ float g_den[TT];
__device__ float g_kv[BB*MM*DVV];
__device__ float g_ksum[BB*MM];
__device__ float g_gkmax;

// sign-correct float atomic max
__device__ __forceinline__ void atomicMaxFloat(float* addr, float v) {
    if (v >= 0.0f) atomicMax((int*)addr, __float_as_int(v));
    else           atomicMin((unsigned int*)addr, __float_as_uint(v));
}

// ---------------- K0: init scratch that gets accumulated into ----------------
__global__ void k0_init() {
    int tid = blockIdx.x * blockDim.x + threadIdx.x;
    int nt  = gridDim.x * blockDim.x;
    if (tid == 0) g_gkmax = __int_as_float(0xff800000); // -inf
    for (int i = tid; i < BB*MM*DVV; i += nt) g_kv[i] = 0.0f;
    for (int i = tid; i < BB*MM;     i += nt) g_ksum[i] = 0.0f;
}

// ---------------- K1: fused QKV GEMM  out = (x @ W + b) * scale --------------
// A: x [TT, DD] row-major.  W: [DD, 128] row-major.  64x64 tiles, 4x4/thread.
__global__ __launch_bounds__(256) void k1_qkv(
    const float* __restrict__ x,
    const float* __restrict__ Wq, const float* __restrict__ bq,
    const float* __restrict__ Wk, const float* __restrict__ bk,
    const float* __restrict__ Wv, const float* __restrict__ bv)
{
    __shared__ float As[16][64];
    __shared__ float Bs[16][64];
    const int row0  = blockIdx.x * 64;
    const int gcol0 = blockIdx.y * 64;      // 0..383
    const int which = gcol0 >> 7;
    const int colbase = gcol0 & 127;
    const float qkscale = 0.29730177875068026f; // 128^-0.25

    const float* W; const float* bias; float* out; float scale;
    if (which == 0)      { W = Wq; bias = bq; out = g_q; scale = qkscale; }
    else if (which == 1) { W = Wk; bias = bk; out = g_k; scale = qkscale; }
    else                 { W = Wv; bias = bv; out = g_v; scale = 1.0f;    }

    const int tid = threadIdx.x;
    const int tx = tid & 15, ty = tid >> 4;
    const int ar = tid >> 2, av = tid & 3;
    float acc[4][4] = {};

    for (int kt = 0; kt < DD; kt += 16) {
        float4 a4 = *(const float4*)(x + (size_t)(row0 + ar)*DD + kt + av*4);
        As[av*4+0][ar] = a4.x; As[av*4+1][ar] = a4.y;
        As[av*4+2][ar] = a4.z; As[av*4+3][ar] = a4.w;
        #pragma unroll
        for (int i = 0; i < 4; i++) {
            int idx = tid + i*256;
            int kk = idx >> 6, c = idx & 63;
            Bs[kk][c] = W[(size_t)(kt + kk)*DKK + colbase + c];
        }
        __syncthreads();
        #pragma unroll
        for (int kk = 0; kk < 16; kk++) {
            float4 a = *(float4*)&As[kk][ty*4];
            float4 b = *(float4*)&Bs[kk][tx*4];
            acc[0][0] += a.x*b.x; acc[0][1] += a.x*b.y; acc[0][2] += a.x*b.z; acc[0][3] += a.x*b.w;
            acc[1][0] += a.y*b.x; acc[1][1] += a.y*b.y; acc[1][2] += a.y*b.z; acc[1][3] += a.y*b.w;
            acc[2][0] += a.z*b.x; acc[2][1] += a.z*b.y; acc[2][2] += a.z*b.z; acc[2][3] += a.z*b.w;
            acc[3][0] += a.w*b.x; acc[3][1] += a.w*b.y; acc[3][2] += a.w*b.z; acc[3][3] += a.w*b.w;
        }
        __syncthreads();
    }
    #pragma unroll
    for (int i = 0; i < 4; i++) {
        #pragma unroll
        for (int j = 0; j < 4; j++) {
            int c = colbase + tx*4 + j;
            out[(size_t)(row0 + ty*4 + i)*DKK + c] = (acc[i][j] + bias[c]) * scale;
        }
    }
}

// ---------------- K1b: row norms of scaled q and k ---------------------------
__global__ __launch_bounds__(256) void k1b_norms() {
    int t = blockIdx.x * 8 + (threadIdx.x >> 5);
    int lane = threadIdx.x & 31;
    {
        float4 a = ((const float4*)(g_q + (size_t)t*DKK))[lane];
        float s = a.x*a.x + a.y*a.y + a.z*a.z + a.w*a.w;
        #pragma unroll
        for (int o = 16; o; o >>= 1) s += __shfl_xor_sync(0xffffffffu, s, o);
        if (lane == 0) g_qn[t] = s;
    }
    {
        float4 a = ((const float4*)(g_k + (size_t)t*DKK))[lane];
        float s = a.x*a.x + a.y*a.y + a.z*a.z + a.w*a.w;
        #pragma unroll
        for (int o = 16; o; o >>= 1) s += __shfl_xor_sync(0xffffffffu, s, o);
        if (lane == 0) g_kn[t] = s;
    }
}

// ---------------- K2: feature projection  p = y @ omega^T - 0.5||y||^2 -------
// z=0 -> q->pq, z=1 -> k->pk.  omega: [MM, DKK] row-major.
__global__ __launch_bounds__(256) void k2_proj(const float* __restrict__ omega) {
    __shared__ float As[16][64];
    __shared__ float Bs[16][64];
    const int row0 = blockIdx.x * 64;
    const int m0   = blockIdx.y * 64;
    const bool isK = blockIdx.z != 0;
    const float* A   = isK ? g_k  : g_q;
    const float* nrm = isK ? g_kn : g_qn;
    float* out       = isK ? g_pk : g_pq;

    const int tid = threadIdx.x;
    const int tx = tid & 15, ty = tid >> 4;
    const int ar = tid >> 2, av = tid & 3;
    float acc[4][4] = {};

    for (int kt = 0; kt < DKK; kt += 16) {
        float4 a4 = *(const float4*)(A + (size_t)(row0 + ar)*DKK + kt + av*4);
        As[av*4+0][ar] = a4.x; As[av*4+1][ar] = a4.y;
        As[av*4+2][ar] = a4.z; As[av*4+3][ar] = a4.w;
        float4 b4 = *(const float4*)(omega + (size_t)(m0 + ar)*DKK + kt + av*4);
        Bs[av*4+0][ar] = b4.x; Bs[av*4+1][ar] = b4.y;
        Bs[av*4+2][ar] = b4.z; Bs[av*4+3][ar] = b4.w;
        __syncthreads();
        #pragma unroll
        for (int kk = 0; kk < 16; kk++) {
            float4 a = *(float4*)&As[kk][ty*4];
            float4 b = *(float4*)&Bs[kk][tx*4];
            acc[0][0] += a.x*b.x; acc[0][1] += a.x*b.y; acc[0][2] += a.x*b.z; acc[0][3] += a.x*b.w;
            acc[1][0] += a.y*b.x; acc[1][1] += a.y*b.y; acc[1][2] += a.y*b.z; acc[1][3] += a.y*b.w;
            acc[2][0] += a.z*b.x; acc[2][1] += a.z*b.y; acc[2][2] += a.z*b.z; acc[2][3] += a.z*b.w;
            acc[3][0] += a.w*b.x; acc[3][1] += a.w*b.y; acc[3][2] += a.w*b.z; acc[3][3] += a.w*b.w;
        }
        __syncthreads();
    }
    #pragma unroll
    for (int i = 0; i < 4; i++) {
        float hn = 0.5f * nrm[row0 + ty*4 + i];
        #pragma unroll
        for (int j = 0; j < 4; j++)
            out[(size_t)(row0 + ty*4 + i)*MM + m0 + tx*4 + j] = acc[i][j] - hn;
    }
}

// ---------------- K3a: phi_q = exp(pq - rowmax)/16 (in place); pk global max -
__global__ __launch_bounds__(256) void k3a() {
    __shared__ float wmax[8];
    int t = blockIdx.x * 8 + (threadIdx.x >> 5);
    int lane = threadIdx.x & 31;
    // pq: per-row max + exp in place
    float* pq = g_pq + (size_t)t*MM;
    float4 v0 = *(float4*)(pq + lane*4);
    float4 v1 = *(float4*)(pq + 128 + lane*4);
    float mx = fmaxf(fmaxf(fmaxf(v0.x, v0.y), fmaxf(v0.z, v0.w)),
                     fmaxf(fmaxf(v1.x, v1.y), fmaxf(v1.z, v1.w)));
    #pragma unroll
    for (int o = 16; o; o >>= 1) mx = fmaxf(mx, __shfl_xor_sync(0xffffffffu, mx, o));
    float4 e0, e1;
    e0.x = expf(v0.x - mx)*0.0625f; e0.y = expf(v0.y - mx)*0.0625f;
    e0.z = expf(v0.z - mx)*0.0625f; e0.w = expf(v0.w - mx)*0.0625f;
    e1.x = expf(v1.x - mx)*0.0625f; e1.y = expf(v1.y - mx)*0.0625f;
    e1.z = expf(v1.z - mx)*0.0625f; e1.w = expf(v1.w - mx)*0.0625f;
    *(float4*)(pq + lane*4) = e0;
    *(float4*)(pq + 128 + lane*4) = e1;
    // pk: contribute to global max
    const float* pk = g_pk + (size_t)t*MM;
    float4 k0 = *(const float4*)(pk + lane*4);
    float4 k1 = *(const float4*)(pk + 128 + lane*4);
    float km = fmaxf(fmaxf(fmaxf(k0.x, k0.y), fmaxf(k0.z, k0.w)),
                     fmaxf(fmaxf(k1.x, k1.y), fmaxf(k1.z, k1.w)));
    #pragma unroll
    for (int o = 16; o; o >>= 1) km = fmaxf(km, __shfl_xor_sync(0xffffffffu, km, o));
    if (lane == 0) wmax[threadIdx.x >> 5] = km;
    __syncthreads();
    if (threadIdx.x == 0) {
        float bm = wmax[0];
        #pragma unroll
        for (int w = 1; w < 8; w++) bm = fmaxf(bm, wmax[w]);
        atomicMaxFloat(&g_gkmax, bm);
    }
}

// ---------------- K3b: phi_k = exp(pk - gmax)/16 (in place) ------------------
__global__ __launch_bounds__(256) void k3b() {
    float gm = g_gkmax;
    size_t n4 = (size_t)TT*MM/4;
    size_t stride = (size_t)gridDim.x * blockDim.x;
    for (size_t i = (size_t)blockIdx.x*blockDim.x + threadIdx.x; i < n4; i += stride) {
        float4 v = ((float4*)g_pk)[i];
        v.x = expf(v.x - gm)*0.0625f; v.y = expf(v.y - gm)*0.0625f;
        v.z = expf(v.z - gm)*0.0625f; v.w = expf(v.w - gm)*0.0625f;
        ((float4*)g_pk)[i] = v;
    }
}

// ---------------- K4: kv[b] += phi_k[b]^T @ v[b]  (split-K over s) -----------
__global__ __launch_bounds__(256) void k4_kv() {
    __shared__ float As[16][64];   // [s_chunk][m]
    __shared__ float Bs[16][64];   // [s_chunk][d]
    const int b  = blockIdx.x;
    const int m0 = (blockIdx.y >> 1) * 64;
    const int d0 = (blockIdx.y & 1) * 64;
    const int s0 = blockIdx.z * 1024;
    const float* Pk = g_pk + (size_t)b*SS*MM;
    const float* V  = g_v  + (size_t)b*SS*DVV;
    const int tid = threadIdx.x;
    const int tx = tid & 15, ty = tid >> 4;
    float acc[4][4] = {};

    for (int kt = 0; kt < 1024; kt += 16) {
        #pragma unroll
        for (int i = 0; i < 4; i++) {
            int idx = tid + i*256;
            int kk = idx >> 6, c = idx & 63;
            As[kk][c] = Pk[(size_t)(s0 + kt + kk)*MM  + m0 + c];
            Bs[kk][c] = V [(size_t)(s0 + kt + kk)*DVV + d0 + c];
        }
        __syncthreads();
        #pragma unroll
        for (int kk = 0; kk < 16; kk++) {
            float4 a = *(float4*)&As[kk][ty*4];
            float4 b4 = *(float4*)&Bs[kk][tx*4];
            acc[0][0] += a.x*b4.x; acc[0][1] += a.x*b4.y; acc[0][2] += a.x*b4.z; acc[0][3] += a.x*b4.w;
            acc[1][0] += a.y*b4.x; acc[1][1] += a.y*b4.y; acc[1][2] += a.y*b4.z; acc[1][3] += a.y*b4.w;
            acc[2][0] += a.z*b4.x; acc[2][1] += a.z*b4.y; acc[2][2] += a.z*b4.z; acc[2][3] += a.z*b4.w;
            acc[3][0] += a.w*b4.x; acc[3][1] += a.w*b4.y; acc[3][2] += a.w*b4.z; acc[3][3] += a.w*b4.w;
        }
        __syncthreads();
    }
    #pragma unroll
    for (int i = 0; i < 4; i++)
        #pragma unroll
        for (int j = 0; j < 4; j++)
            atomicAdd(&g_kv[(b*MM + m0 + ty*4 + i)*DVV + d0 + tx*4 + j], acc[i][j]);
}

// ---------------- K4b: ksum[b,m] = sum_s phi_k --------------------------------
__global__ __launch_bounds__(256) void k4b_ksum() {
    int b = blockIdx.x;
    int chunk = blockIdx.y;            // 32 chunks of 128 s
    int m = threadIdx.x;               // 256
    const float* Pk = g_pk + ((size_t)b*SS + chunk*128)*MM + m;
    float s = 0.0f;
    #pragma unroll 8
    for (int i = 0; i < 128; i++) s += Pk[(size_t)i*MM];
    atomicAdd(&g_ksum[b*MM + m], s);
}

// ---------------- K5a: den[t] = dot(phi_q[t], ksum[b]) + eps ------------------
__global__ __launch_bounds__(256) void k5a_den() {
    int t = blockIdx.x * 8 + (threadIdx.x >> 5);
    int lane = threadIdx.x & 31;
    int b = t >> 12; // / 4096
    const float* pq = g_pq + (size_t)t*MM;
    const float* ks = g_ksum + b*MM;
    float4 p0 = *(const float4*)(pq + lane*4);
    float4 p1 = *(const float4*)(pq + 128 + lane*4);
    float4 k0 = *(const float4*)(ks + lane*4);
    float4 k1 = *(const float4*)(ks + 128 + lane*4);
    float s = p0.x*k0.x + p0.y*k0.y + p0.z*k0.z + p0.w*k0.w
            + p1.x*k1.x + p1.y*k1.y + p1.z*k1.z + p1.w*k1.w;
    #pragma unroll
    for (int o = 16; o; o >>= 1) s += __shfl_xor_sync(0xffffffffu, s, o);
    if (lane == 0) g_den[t] = s + EPSV;
}

// ---------------- K5: out = (phi_q @ kv[b]) / den -----------------------------
__global__ __launch_bounds__(256) void k5_out(float* __restrict__ out) {
    __shared__ float As[16][64];
    __shared__ float Bs[16][64];
    const int row0 = blockIdx.x * 64;
    const int d0   = blockIdx.y * 64;
    const int b    = row0 >> 12;
    const float* KV = g_kv + b*MM*DVV;
    const int tid = threadIdx.x;
    const int tx = tid & 15, ty = tid >> 4;
    const int ar = tid >> 2, av = tid & 3;
    float acc[4][4] = {};

    for (int kt = 0; kt < MM; kt += 16) {
        float4 a4 = *(const float4*)(g_pq + (size_t)(row0 + ar)*MM + kt + av*4);
        As[av*4+0][ar] = a4.x; As[av*4+1][ar] = a4.y;
        As[av*4+2][ar] = a4.z; As[av*4+3][ar] = a4.w;
        #pragma unroll
        for (int i = 0; i < 4; i++) {
            int idx = tid + i*256;
            int kk = idx >> 6, c = idx & 63;
            Bs[kk][c] = KV[(kt + kk)*DVV + d0 + c];
        }
        __syncthreads();
        #pragma unroll
        for (int kk = 0; kk < 16; kk++) {
            float4 a = *(float4*)&As[kk][ty*4];
            float4 b4 = *(float4*)&Bs[kk][tx*4];
            acc[0][0] += a.x*b4.x; acc[0][1] += a.x*b4.y; acc[0][2] += a.x*b4.z; acc[0][3] += a.x*b4.w;
            acc[1][0] += a.y*b4.x; acc[1][1] += a.y*b4.y; acc[1][2] += a.y*b4.z; acc[1][3] += a.y*b4.w;
            acc[2][0] += a.z*b4.x; acc[2][1] += a.z*b4.y; acc[2][2] += a.z*b4.z; acc[2][3] += a.z*b4.w;
            acc[3][0] += a.w*b4.x; acc[3][1] += a.w*b4.y; acc[3][2] += a.w*b4.z; acc[3][3] += a.w*b4.w;
        }
        __syncthreads();
    }
    #pragma unroll
    for (int i = 0; i < 4; i++) {
        float inv = 1.0f / g_den[row0 + ty*4 + i];
        #pragma unroll
        for (int j = 0; j < 4; j++)
            out[(size_t)(row0 + ty*4 + i)*DVV + d0 + tx*4 + j] = acc[i][j] * inv;
    }
}

// ---------------- launch ------------------------------------------------------
extern "C" void kernel_launch(void* const* d_in, const int* in_sizes, int n_in,
                              void* d_out, int out_size) {
    const float* x     = (const float*)d_in[0];
    const float* Wq    = (const float*)d_in[1];
    const float* bq    = (const float*)d_in[2];
    const float* Wk    = (const float*)d_in[3];
    const float* bk    = (const float*)d_in[4];
    const float* Wv    = (const float*)d_in[5];
    const float* bv    = (const float*)d_in[6];
    const float* omega = (const float*)d_in[7];
    float* out = (float*)d_out;

    k0_init<<<64, 256>>>();
    k1_qkv<<<dim3(512, 6), 256>>>(x, Wq, bq, Wk, bk, Wv, bv);
    k1b_norms<<<TT/8, 256>>>();
    k2_proj<<<dim3(512, 4, 2), 256>>>(omega);
    k3a<<<TT/8, 256>>>();
    k3b<<<2048, 256>>>();
    k4_kv<<<dim3(8, 8, 4), 256>>>();
    k4b_ksum<<<dim3(8, 32), 256>>>();
    k5a_den<<<TT/8, 256>>>();
    k5_out<<<dim3(512, 2), 256>>>(out);
}

// round 6
// speedup vs baseline: 1.8147x; 1.8147x over previous
#include <cuda_runtime.h>
#include <math.h>
#include <stdint.h>

#define BB 8
#define SS 4096
#define TT (BB*SS)          // 32768 tokens
#define DD 1024
#define DKK 128
#define DVV 128
#define MM 256
#define EPSV 1e-6f

#define LDR 36              // row-major smem leading dim (floats)
#define LDT 136             // k-major smem leading dim (floats)
#define TILE_B 18432        // one 128x32 tile w/ pad, bytes
#define TILE_F 4608         // same in floats
#define STG4_B (4*TILE_B)   // 4-tile stage (Ah,Bh,Al,Bl)
#define STG2_B (2*TILE_B)   // 2-tile stage (A,B)
#define SMEM4 (2*STG4_B)    // 147456
#define SMEM2 (2*STG2_B)    // 73728

// ---------------- scratch (device globals; no allocation allowed) -------------
__device__ float g_xh[(size_t)TT*DD];
__device__ float g_xl[(size_t)TT*DD];
__device__ float g_Wh[384*DD];              // W transposed [n][k]
__device__ float g_Wl[384*DD];
__device__ float g_omh[MM*DKK];
__device__ float g_oml[MM*DKK];
__device__ float g_qh[(size_t)TT*DKK];
__device__ float g_ql[(size_t)TT*DKK];
__device__ float g_kh[(size_t)TT*DKK];
__device__ float g_kl[(size_t)TT*DKK];
__device__ float g_vr[(size_t)TT*DVV];      // v, single tf32 rounding
__device__ float g_pq[(size_t)TT*MM];       // logits, then phi_q (tf32-rounded)
__device__ float g_pk[(size_t)TT*MM];
__device__ float g_qn[TT];
__device__ float g_kn[TT];
__device__ float g_den[TT];
__device__ float g_kvT[BB*DVV*MM];          // kv transposed [b][d][m]
__device__ float g_ksum[BB*MM];
__device__ float g_gkmax;

// ---------------- helpers -----------------------------------------------------
__device__ __forceinline__ uint32_t smem_u32(const void* p) {
    uint32_t a;
    asm("{ .reg .u64 t; cvta.to.shared.u64 t, %1; cvt.u32.u64 %0, t; }" : "=r"(a) : "l"(p));
    return a;
}
__device__ __forceinline__ float rndtf(float x) {
    uint32_t r; asm("cvt.rna.tf32.f32 %0, %1;" : "=r"(r) : "f"(x));
    return __uint_as_float(r);
}
__device__ __forceinline__ void atomicMaxFloat(float* addr, float v) {
    if (v >= 0.0f) atomicMax((int*)addr, __float_as_int(v));
    else           atomicMin((unsigned int*)addr, __float_as_uint(v));
}
__device__ __forceinline__ void cpa16(uint32_t d, const float* s) {
    asm volatile("cp.async.cg.shared.global [%0], [%1], 16;" :: "r"(d), "l"(s));
}
#define CP_COMMIT() asm volatile("cp.async.commit_group;" ::: "memory")

#define MMA8(d, a, b) \
    asm volatile("mma.sync.aligned.m16n8k8.row.col.f32.tf32.tf32.f32 " \
        "{%0,%1,%2,%3}, {%4,%5,%6,%7}, {%8,%9}, {%0,%1,%2,%3};" \
        : "+f"((d)[0]), "+f"((d)[1]), "+f"((d)[2]), "+f"((d)[3]) \
        : "r"((a)[0]), "r"((a)[1]), "r"((a)[2]), "r"((a)[3]), \
          "r"((b)[0]), "r"((b)[1]))

// load 128 rows x 32 cols (floats) row-major source into smem layout R
__device__ __forceinline__ void ldR4(uint32_t sb, const float* src, int ldg, int tid) {
    #pragma unroll
    for (int t = 0; t < 4; t++) {
        int idx = tid + t*256, r = idx >> 3, c = idx & 7;
        cpa16(sb + (uint32_t)(r*LDR + c*4)*4u, src + (size_t)r*ldg + c*4);
    }
}
// load 32 rows x 128 cols (floats) row-major source into smem layout T
__device__ __forceinline__ void ldT4(uint32_t sb, const float* src, int ldg, int tid) {
    #pragma unroll
    for (int t = 0; t < 4; t++) {
        int idx = tid + t*256, r = idx >> 5, c = idx & 31;
        cpa16(sb + (uint32_t)(r*LDT + c*4)*4u, src + (size_t)r*ldg + c*4);
    }
}

// 64x32 warp tile over one KC=32 chunk; smem layout R ([row][k], ld 36)
__device__ __forceinline__ void coreR(const float* As, const float* Bs,
                                      float acc[4][4][4], int wm, int wn, int gid, int tig) {
    #pragma unroll
    for (int k8 = 0; k8 < 32; k8 += 8) {
        uint32_t a[4][4], b[4][2];
        #pragma unroll
        for (int im = 0; im < 4; im++) {
            int rb = wm + im*16;
            a[im][0] = __float_as_uint(As[(rb+gid  )*LDR + k8+tig  ]);
            a[im][1] = __float_as_uint(As[(rb+gid+8)*LDR + k8+tig  ]);
            a[im][2] = __float_as_uint(As[(rb+gid  )*LDR + k8+tig+4]);
            a[im][3] = __float_as_uint(As[(rb+gid+8)*LDR + k8+tig+4]);
        }
        #pragma unroll
        for (int jn = 0; jn < 4; jn++) {
            int nb = wn + jn*8;
            b[jn][0] = __float_as_uint(Bs[(nb+gid)*LDR + k8+tig  ]);
            b[jn][1] = __float_as_uint(Bs[(nb+gid)*LDR + k8+tig+4]);
        }
        #pragma unroll
        for (int im = 0; im < 4; im++)
            #pragma unroll
            for (int jn = 0; jn < 4; jn++)
                MMA8(acc[im][jn], a[im], b[jn]);
    }
}
// same but smem layout T ([k][row], ld 136)
__device__ __forceinline__ void coreT(const float* As, const float* Bs,
                                      float acc[4][4][4], int wm, int wn, int gid, int tig) {
    #pragma unroll
    for (int k8 = 0; k8 < 32; k8 += 8) {
        uint32_t a[4][4], b[4][2];
        #pragma unroll
        for (int im = 0; im < 4; im++) {
            int rb = wm + im*16;
            a[im][0] = __float_as_uint(As[(k8+tig  )*LDT + rb+gid  ]);
            a[im][1] = __float_as_uint(As[(k8+tig  )*LDT + rb+gid+8]);
            a[im][2] = __float_as_uint(As[(k8+tig+4)*LDT + rb+gid  ]);
            a[im][3] = __float_as_uint(As[(k8+tig+4)*LDT + rb+gid+8]);
        }
        #pragma unroll
        for (int jn = 0; jn < 4; jn++) {
            int nb = wn + jn*8;
            b[jn][0] = __float_as_uint(Bs[(k8+tig  )*LDT + nb+gid]);
            b[jn][1] = __float_as_uint(Bs[(k8+tig+4)*LDT + nb+gid]);
        }
        #pragma unroll
        for (int im = 0; im < 4; im++)
            #pragma unroll
            for (int jn = 0; jn < 4; jn++)
                MMA8(acc[im][jn], a[im], b[jn]);
    }
}

// ---------------- prep kernels ------------------------------------------------
__global__ __launch_bounds__(256) void k_prep_w(
    const float* __restrict__ Wq, const float* __restrict__ Wk, const float* __restrict__ Wv) {
    int idx = blockIdx.x * 256 + threadIdx.x;          // 0..393215
    int row = idx >> 10, k = idx & 1023;
    const float* W = (row < 128) ? Wq : (row < 256) ? Wk : Wv;
    int n = row & 127;
    float v = W[(size_t)k * DKK + n];
    float h = rndtf(v);
    g_Wh[idx] = h;
    g_Wl[idx] = rndtf(v - h);
}
__global__ __launch_bounds__(256) void k_prep_om(const float* __restrict__ om) {
    int idx = blockIdx.x * 256 + threadIdx.x;          // 0..32767
    float v = om[idx];
    float h = rndtf(v);
    g_omh[idx] = h;
    g_oml[idx] = rndtf(v - h);
}
__global__ __launch_bounds__(256) void k_prep_x(const float* __restrict__ x) {
    size_t i = (size_t)blockIdx.x * 256 + threadIdx.x;
    size_t n4 = (size_t)TT*DD/4, stride = (size_t)gridDim.x * 256;
    const float4* x4 = (const float4*)x;
    float4* h4 = (float4*)g_xh;
    float4* l4 = (float4*)g_xl;
    for (; i < n4; i += stride) {
        float4 v = x4[i];
        float4 h, l;
        h.x = rndtf(v.x); l.x = rndtf(v.x - h.x);
        h.y = rndtf(v.y); l.y = rndtf(v.y - h.y);
        h.z = rndtf(v.z); l.z = rndtf(v.z - h.z);
        h.w = rndtf(v.w); l.w = rndtf(v.w - h.w);
        h4[i] = h; l4[i] = l;
    }
}
__global__ void k0_init() {
    int tid = blockIdx.x * blockDim.x + threadIdx.x;
    int nt  = gridDim.x * blockDim.x;
    if (tid == 0) g_gkmax = __int_as_float(0xff800000);
    for (int i = tid; i < BB*DVV*MM; i += nt) g_kvT[i] = 0.0f;
    for (int i = tid; i < BB*MM;     i += nt) g_ksum[i] = 0.0f;
}

// ---------------- K1: QKV GEMM, 3xTF32 for q/k, 1x for v ----------------------
// blockIdx.y: 0=q, 1=k, 2=v
__global__ __launch_bounds__(256,1) void k1_mma(
    const float* __restrict__ bq, const float* __restrict__ bk, const float* __restrict__ bv) {
    extern __shared__ char smarr[];
    uint32_t sb = smem_u32(smarr);
    const int tid = threadIdx.x, lane = tid & 31, wid = tid >> 5;
    const int gid = lane >> 2, tig = lane & 3;
    const int wm = (wid >> 2)*64, wn = (wid & 3)*32;
    const int row0 = blockIdx.x * 128;
    const int which = blockIdx.y;
    const bool isV = (which == 2);
    const float* Ah = g_xh + (size_t)row0*DD;
    const float* Al = g_xl + (size_t)row0*DD;
    const float* Bh = g_Wh + (size_t)which*128*DD;
    const float* Bl = g_Wl + (size_t)which*128*DD;
    float acc[4][4][4] = {};

    // stage layout (floats): Ah @0, Bh @TILE_F, Al @2*TILE_F, Bl @3*TILE_F
    {
        ldR4(sb, Ah, DD, tid);
        ldR4(sb + TILE_B, Bh, DD, tid);
        if (!isV) { ldR4(sb + 2*TILE_B, Al, DD, tid); ldR4(sb + 3*TILE_B, Bl, DD, tid); }
        CP_COMMIT();
    }
    for (int c = 0; c < 32; c++) {
        if (c+1 < 32) {
            uint32_t st = sb + ((c+1)&1)*STG4_B;
            ldR4(st, Ah + (c+1)*32, DD, tid);
            ldR4(st + TILE_B, Bh + (c+1)*32, DD, tid);
            if (!isV) {
                ldR4(st + 2*TILE_B, Al + (c+1)*32, DD, tid);
                ldR4(st + 3*TILE_B, Bl + (c+1)*32, DD, tid);
            }
            CP_COMMIT();
            asm volatile("cp.async.wait_group 1;" ::: "memory");
        } else {
            asm volatile("cp.async.wait_group 0;" ::: "memory");
        }
        __syncthreads();
        const float* S = (const float*)(smarr + (c&1)*STG4_B);
        coreR(S, S + TILE_F, acc, wm, wn, gid, tig);                   // Ah*Bh
        if (!isV) {
            coreR(S, S + 3*TILE_F, acc, wm, wn, gid, tig);             // Ah*Bl
            coreR(S + 2*TILE_F, S + TILE_F, acc, wm, wn, gid, tig);    // Al*Bh
        }
        __syncthreads();
    }
    const float QKS = 0.29730177875068026f;
    const float* bias = (which == 0) ? bq : (which == 1) ? bk : bv;
    float scale = isV ? 1.0f : QKS;
    float* oh = (which == 0) ? g_qh : (which == 1) ? g_kh : g_vr;
    float* ol = (which == 0) ? g_ql : g_kl;   // unused for v
    #pragma unroll
    for (int im = 0; im < 4; im++) {
        #pragma unroll
        for (int jn = 0; jn < 4; jn++) {
            int row = row0 + wm + im*16 + gid;
            int col = wn + jn*8 + tig*2;
            float b0 = bias[col], b1 = bias[col+1];
            #pragma unroll
            for (int half = 0; half < 2; half++) {
                float f0 = (acc[im][jn][half*2+0] + b0)*scale;
                float f1 = (acc[im][jn][half*2+1] + b1)*scale;
                size_t off = (size_t)(row + half*8)*128 + col;
                float2 h, l;
                h.x = rndtf(f0); h.y = rndtf(f1);
                *(float2*)(oh + off) = h;
                if (!isV) {
                    l.x = rndtf(f0 - h.x); l.y = rndtf(f1 - h.y);
                    *(float2*)(ol + off) = l;
                }
            }
        }
    }
}

// ---------------- K1b: row norms of full q, k (hi+lo) -------------------------
__global__ __launch_bounds__(256) void k1b_norms() {
    int t = blockIdx.x * 8 + (threadIdx.x >> 5);
    int lane = threadIdx.x & 31;
    {
        float4 h = ((const float4*)(g_qh + (size_t)t*DKK))[lane];
        float4 l = ((const float4*)(g_ql + (size_t)t*DKK))[lane];
        float ax = h.x+l.x, ay = h.y+l.y, az = h.z+l.z, aw = h.w+l.w;
        float s = ax*ax + ay*ay + az*az + aw*aw;
        #pragma unroll
        for (int o = 16; o; o >>= 1) s += __shfl_xor_sync(0xffffffffu, s, o);
        if (lane == 0) g_qn[t] = s;
    }
    {
        float4 h = ((const float4*)(g_kh + (size_t)t*DKK))[lane];
        float4 l = ((const float4*)(g_kl + (size_t)t*DKK))[lane];
        float ax = h.x+l.x, ay = h.y+l.y, az = h.z+l.z, aw = h.w+l.w;
        float s = ax*ax + ay*ay + az*az + aw*aw;
        #pragma unroll
        for (int o = 16; o; o >>= 1) s += __shfl_xor_sync(0xffffffffu, s, o);
        if (lane == 0) g_kn[t] = s;
    }
}

// ---------------- K2: feature projection, 3xTF32 ------------------------------
__global__ __launch_bounds__(256,1) void k2_mma() {
    extern __shared__ char smarr[];
    uint32_t sb = smem_u32(smarr);
    const int tid = threadIdx.x, lane = tid & 31, wid = tid >> 5;
    const int gid = lane >> 2, tig = lane & 3;
    const int wm = (wid >> 2)*64, wn = (wid & 3)*32;
    const int row0 = blockIdx.x * 128, n0 = blockIdx.y * 128;
    const bool isK = blockIdx.z != 0;
    const float* Ah = (isK ? g_kh : g_qh) + (size_t)row0*DKK;
    const float* Al = (isK ? g_kl : g_ql) + (size_t)row0*DKK;
    const float* Bh = g_omh + (size_t)n0*DKK;
    const float* Bl = g_oml + (size_t)n0*DKK;
    const float* nrm  = isK ? g_kn : g_qn;
    float* out        = isK ? g_pk : g_pq;
    float acc[4][4][4] = {};

    {
        ldR4(sb, Ah, DKK, tid);
        ldR4(sb + TILE_B, Bh, DKK, tid);
        ldR4(sb + 2*TILE_B, Al, DKK, tid);
        ldR4(sb + 3*TILE_B, Bl, DKK, tid);
        CP_COMMIT();
    }
    for (int c = 0; c < 4; c++) {
        if (c+1 < 4) {
            uint32_t st = sb + ((c+1)&1)*STG4_B;
            ldR4(st, Ah + (c+1)*32, DKK, tid);
            ldR4(st + TILE_B, Bh + (c+1)*32, DKK, tid);
            ldR4(st + 2*TILE_B, Al + (c+1)*32, DKK, tid);
            ldR4(st + 3*TILE_B, Bl + (c+1)*32, DKK, tid);
            CP_COMMIT();
            asm volatile("cp.async.wait_group 1;" ::: "memory");
        } else {
            asm volatile("cp.async.wait_group 0;" ::: "memory");
        }
        __syncthreads();
        const float* S = (const float*)(smarr + (c&1)*STG4_B);
        coreR(S, S + TILE_F, acc, wm, wn, gid, tig);
        coreR(S, S + 3*TILE_F, acc, wm, wn, gid, tig);
        coreR(S + 2*TILE_F, S + TILE_F, acc, wm, wn, gid, tig);
        __syncthreads();
    }
    #pragma unroll
    for (int im = 0; im < 4; im++) {
        #pragma unroll
        for (int jn = 0; jn < 4; jn++) {
            int row = row0 + wm + im*16 + gid;
            int col = n0 + wn + jn*8 + tig*2;
            float hn0 = 0.5f * nrm[row], hn1 = 0.5f * nrm[row+8];
            float2 v;
            v.x = acc[im][jn][0] - hn0; v.y = acc[im][jn][1] - hn0;
            *(float2*)(out + (size_t)row*MM + col) = v;
            v.x = acc[im][jn][2] - hn1; v.y = acc[im][jn][3] - hn1;
            *(float2*)(out + (size_t)(row+8)*MM + col) = v;
        }
    }
}

// ---------------- K3a: phi_q = rnd(exp(pq - rowmax)/16); pk global max --------
__global__ __launch_bounds__(256) void k3a() {
    __shared__ float wmax[8];
    int t = blockIdx.x * 8 + (threadIdx.x >> 5);
    int lane = threadIdx.x & 31;
    float* pq = g_pq + (size_t)t*MM;
    float4 v0 = *(float4*)(pq + lane*4);
    float4 v1 = *(float4*)(pq + 128 + lane*4);
    float mx = fmaxf(fmaxf(fmaxf(v0.x, v0.y), fmaxf(v0.z, v0.w)),
                     fmaxf(fmaxf(v1.x, v1.y), fmaxf(v1.z, v1.w)));
    #pragma unroll
    for (int o = 16; o; o >>= 1) mx = fmaxf(mx, __shfl_xor_sync(0xffffffffu, mx, o));
    float4 e0, e1;
    e0.x = rndtf(expf(v0.x - mx)*0.0625f); e0.y = rndtf(expf(v0.y - mx)*0.0625f);
    e0.z = rndtf(expf(v0.z - mx)*0.0625f); e0.w = rndtf(expf(v0.w - mx)*0.0625f);
    e1.x = rndtf(expf(v1.x - mx)*0.0625f); e1.y = rndtf(expf(v1.y - mx)*0.0625f);
    e1.z = rndtf(expf(v1.z - mx)*0.0625f); e1.w = rndtf(expf(v1.w - mx)*0.0625f);
    *(float4*)(pq + lane*4) = e0;
    *(float4*)(pq + 128 + lane*4) = e1;
    const float* pk = g_pk + (size_t)t*MM;
    float4 k0 = *(const float4*)(pk + lane*4);
    float4 k1 = *(const float4*)(pk + 128 + lane*4);
    float km = fmaxf(fmaxf(fmaxf(k0.x, k0.y), fmaxf(k0.z, k0.w)),
                     fmaxf(fmaxf(k1.x, k1.y), fmaxf(k1.z, k1.w)));
    #pragma unroll
    for (int o = 16; o; o >>= 1) km = fmaxf(km, __shfl_xor_sync(0xffffffffu, km, o));
    if (lane == 0) wmax[threadIdx.x >> 5] = km;
    __syncthreads();
    if (threadIdx.x == 0) {
        float bm = wmax[0];
        #pragma unroll
        for (int w = 1; w < 8; w++) bm = fmaxf(bm, wmax[w]);
        atomicMaxFloat(&g_gkmax, bm);
    }
}

// ---------------- K3b: phi_k = rnd(exp(pk - gmax)/16) -------------------------
__global__ __launch_bounds__(256) void k3b() {
    float gm = g_gkmax;
    size_t n4 = (size_t)TT*MM/4;
    size_t stride = (size_t)gridDim.x * blockDim.x;
    for (size_t i = (size_t)blockIdx.x*blockDim.x + threadIdx.x; i < n4; i += stride) {
        float4 v = ((float4*)g_pk)[i];
        v.x = rndtf(expf(v.x - gm)*0.0625f); v.y = rndtf(expf(v.y - gm)*0.0625f);
        v.z = rndtf(expf(v.z - gm)*0.0625f); v.w = rndtf(expf(v.w - gm)*0.0625f);
        ((float4*)g_pk)[i] = v;
    }
}

// ---------------- K4: kvT[b][d][m] += sum_s phi_k[s][m] v[s][d] ---------------
__global__ __launch_bounds__(256,2) void k4_mma() {
    extern __shared__ char smarr[];
    uint32_t sb = smem_u32(smarr);
    const int tid = threadIdx.x, lane = tid & 31, wid = tid >> 5;
    const int gid = lane >> 2, tig = lane & 3;
    const int wm = (wid >> 2)*64, wn = (wid & 3)*32;
    const int b = blockIdx.x, m0 = blockIdx.y * 128, sp = blockIdx.z;
    const float* Asrc = g_pk + ((size_t)b*SS + sp*512)*MM + m0;   // rows=s, cols=m
    const float* Bsrc = g_vr + ((size_t)b*SS + sp*512)*DVV;       // rows=s, cols=d
    float acc[4][4][4] = {};

    { ldT4(sb, Asrc, MM, tid); ldT4(sb + TILE_B, Bsrc, DVV, tid); CP_COMMIT(); }
    for (int c = 0; c < 16; c++) {
        if (c+1 < 16) {
            uint32_t st = sb + ((c+1)&1)*STG2_B;
            ldT4(st, Asrc + (size_t)(c+1)*32*MM, MM, tid);
            ldT4(st + TILE_B, Bsrc + (size_t)(c+1)*32*DVV, DVV, tid);
            CP_COMMIT();
            asm volatile("cp.async.wait_group 1;" ::: "memory");
        } else {
            asm volatile("cp.async.wait_group 0;" ::: "memory");
        }
        __syncthreads();
        const float* S = (const float*)(smarr + (c&1)*STG2_B);
        coreT(S, S + TILE_F, acc, wm, wn, gid, tig);
        __syncthreads();
    }
    float* kvb = g_kvT + (size_t)b*DVV*MM;
    #pragma unroll
    for (int im = 0; im < 4; im++) {
        #pragma unroll
        for (int jn = 0; jn < 4; jn++) {
            int m = m0 + wm + im*16 + gid;
            int d = wn + jn*8 + tig*2;
            atomicAdd(&kvb[(size_t)d*MM + m],       acc[im][jn][0]);
            atomicAdd(&kvb[(size_t)(d+1)*MM + m],   acc[im][jn][1]);
            atomicAdd(&kvb[(size_t)d*MM + m+8],     acc[im][jn][2]);
            atomicAdd(&kvb[(size_t)(d+1)*MM + m+8], acc[im][jn][3]);
        }
    }
}

// ---------------- K4c: round kvT in place -------------------------------------
__global__ __launch_bounds__(256) void k4c_round() {
    int i = blockIdx.x * 256 + threadIdx.x;
    int n = BB*DVV*MM;
    for (; i < n; i += gridDim.x * 256) g_kvT[i] = rndtf(g_kvT[i]);
}

// ---------------- K4b: ksum[b,m] = sum_s phi_k --------------------------------
__global__ __launch_bounds__(256) void k4b_ksum() {
    int b = blockIdx.x, chunk = blockIdx.y, m = threadIdx.x;
    const float* Pk = g_pk + ((size_t)b*SS + chunk*128)*MM + m;
    float s = 0.0f;
    #pragma unroll 8
    for (int i = 0; i < 128; i++) s += Pk[(size_t)i*MM];
    atomicAdd(&g_ksum[b*MM + m], s);
}

// ---------------- K5a: den[t] = dot(phi_q[t], ksum[b]) + eps ------------------
__global__ __launch_bounds__(256) void k5a_den() {
    int t = blockIdx.x * 8 + (threadIdx.x >> 5);
    int lane = threadIdx.x & 31;
    int b = t >> 12;
    const float* pq = g_pq + (size_t)t*MM;
    const float* ks = g_ksum + b*MM;
    float4 p0 = *(const float4*)(pq + lane*4);
    float4 p1 = *(const float4*)(pq + 128 + lane*4);
    float4 k0 = *(const float4*)(ks + lane*4);
    float4 k1 = *(const float4*)(ks + 128 + lane*4);
    float s = p0.x*k0.x + p0.y*k0.y + p0.z*k0.z + p0.w*k0.w
            + p1.x*k1.x + p1.y*k1.y + p1.z*k1.z + p1.w*k1.w;
    #pragma unroll
    for (int o = 16; o; o >>= 1) s += __shfl_xor_sync(0xffffffffu, s, o);
    if (lane == 0) g_den[t] = s + EPSV;
}

// ---------------- K5: out = (phi_q @ kv) / den --------------------------------
__global__ __launch_bounds__(256,2) void k5_mma(float* __restrict__ out) {
    extern __shared__ char smarr[];
    uint32_t sb = smem_u32(smarr);
    const int tid = threadIdx.x, lane = tid & 31, wid = tid >> 5;
    const int gid = lane >> 2, tig = lane & 3;
    const int wm = (wid >> 2)*64, wn = (wid & 3)*32;
    const int row0 = blockIdx.x * 128;
    const int b = blockIdx.x >> 5;
    const float* Asrc = g_pq + (size_t)row0*MM;                 // rows=t, cols=m
    const float* Bsrc = g_kvT + (size_t)b*DVV*MM;               // rows=d, cols=m
    float acc[4][4][4] = {};

    { ldR4(sb, Asrc, MM, tid); ldR4(sb + TILE_B, Bsrc, MM, tid); CP_COMMIT(); }
    for (int c = 0; c < 8; c++) {
        if (c+1 < 8) {
            uint32_t st = sb + ((c+1)&1)*STG2_B;
            ldR4(st, Asrc + (c+1)*32, MM, tid);
            ldR4(st + TILE_B, Bsrc + (c+1)*32, MM, tid);
            CP_COMMIT();
            asm volatile("cp.async.wait_group 1;" ::: "memory");
        } else {
            asm volatile("cp.async.wait_group 0;" ::: "memory");
        }
        __syncthreads();
        const float* S = (const float*)(smarr + (c&1)*STG2_B);
        coreR(S, S + TILE_F, acc, wm, wn, gid, tig);
        __syncthreads();
    }
    #pragma unroll
    for (int im = 0; im < 4; im++) {
        #pragma unroll
        for (int jn = 0; jn < 4; jn++) {
            int row = row0 + wm + im*16 + gid;
            int col = wn + jn*8 + tig*2;
            float inv0 = 1.0f / g_den[row], inv1 = 1.0f / g_den[row+8];
            float2 v;
            v.x = acc[im][jn][0]*inv0; v.y = acc[im][jn][1]*inv0;
            *(float2*)(out + (size_t)row*DVV + col) = v;
            v.x = acc[im][jn][2]*inv1; v.y = acc[im][jn][3]*inv1;
            *(float2*)(out + (size_t)(row+8)*DVV + col) = v;
        }
    }
}

// ---------------- launch ------------------------------------------------------
extern "C" void kernel_launch(void* const* d_in, const int* in_sizes, int n_in,
                              void* d_out, int out_size) {
    const float* x     = (const float*)d_in[0];
    const float* Wq    = (const float*)d_in[1];
    const float* bq    = (const float*)d_in[2];
    const float* Wk    = (const float*)d_in[3];
    const float* bk    = (const float*)d_in[4];
    const float* Wv    = (const float*)d_in[5];
    const float* bv    = (const float*)d_in[6];
    const float* omega = (const float*)d_in[7];
    float* out = (float*)d_out;

    cudaFuncSetAttribute(k1_mma, cudaFuncAttributeMaxDynamicSharedMemorySize, SMEM4);
    cudaFuncSetAttribute(k2_mma, cudaFuncAttributeMaxDynamicSharedMemorySize, SMEM4);
    cudaFuncSetAttribute(k4_mma, cudaFuncAttributeMaxDynamicSharedMemorySize, SMEM2);
    cudaFuncSetAttribute(k5_mma, cudaFuncAttributeMaxDynamicSharedMemorySize, SMEM2);

    k_prep_w<<<1536, 256>>>(Wq, Wk, Wv);
    k_prep_om<<<128, 256>>>(omega);
    k_prep_x<<<8192, 256>>>(x);
    k0_init<<<64, 256>>>();
    k1_mma<<<dim3(256, 3), 256, SMEM4>>>(bq, bk, bv);
    k1b_norms<<<TT/8, 256>>>();
    k2_mma<<<dim3(256, 2, 2), 256, SMEM4>>>();
    k3a<<<TT/8, 256>>>();
    k3b<<<2048, 256>>>();
    k4_mma<<<dim3(8, 2, 8), 256, SMEM2>>>();
    k4c_round<<<256, 256>>>();
    k4b_ksum<<<dim3(8, 32), 256>>>();
    k5a_den<<<TT/8, 256>>>();
    k5_mma<<<256, 256, SMEM2>>>(out);
}

// round 7
// speedup vs baseline: 1.8355x; 1.0115x over previous
#include <cuda_runtime.h>
#include <math.h>
#include <stdint.h>

#define BB 8
#define SS 4096
#define TT (BB*SS)          // 32768 tokens
#define DD 1024
#define DKK 128
#define DVV 128
#define MM 256
#define EPSV 1e-6f

#define LDR 36              // row-major smem leading dim (floats)
#define LDT 136             // k-major smem leading dim (floats)
#define TILE_B 18432        // one 128x32 tile w/ pad, bytes
#define TILE_F 4608         // same in floats
#define QK_STG (5*TILE_B)   // Xr, Bqh, Bql, Bkh, Bkl
#define SMEM_QK (2*QK_STG + 2*TILE_B)    // + single-buffered Ah, Al = 221184
#define V_STG (2*TILE_B)    // Xr, Bvh
#define SMEM_V (2*V_STG + TILE_B)        // + Ah = 92160
#define K2_STG (6*TILE_B)   // Ah, Al, Bh0, Bl0, Bh1, Bl1
#define SMEM_K2 (2*K2_STG)               // 221184
#define STG2_B (2*TILE_B)
#define SMEM2 (2*STG2_B)                 // 73728 (k4, k5)

// ---------------- scratch (device globals; no allocation allowed) -------------
__device__ float g_Wh[384*DD];              // W transposed [n][k] hi
__device__ float g_Wl[384*DD];              // lo
__device__ float g_omh[MM*DKK];
__device__ float g_oml[MM*DKK];
__device__ float g_qh[(size_t)TT*DKK];
__device__ float g_ql[(size_t)TT*DKK];
__device__ float g_kh[(size_t)TT*DKK];
__device__ float g_kl[(size_t)TT*DKK];
__device__ float g_vr[(size_t)TT*DVV];      // v, single tf32 rounding
__device__ float g_pq[(size_t)TT*MM];       // logits, then phi_q (tf32-rounded)
__device__ float g_pk[(size_t)TT*MM];
__device__ float g_qn[TT];
__device__ float g_kn[TT];
__device__ float g_den[TT];
__device__ float g_kvT[BB*DVV*MM];          // kv transposed [b][d][m]
__device__ float g_ksum[BB*MM];
__device__ float g_gkmax;

// ---------------- helpers -----------------------------------------------------
__device__ __forceinline__ uint32_t smem_u32(const void* p) {
    uint32_t a;
    asm("{ .reg .u64 t; cvta.to.shared.u64 t, %1; cvt.u32.u64 %0, t; }" : "=r"(a) : "l"(p));
    return a;
}
__device__ __forceinline__ float rndtf(float x) {
    uint32_t r; asm("cvt.rna.tf32.f32 %0, %1;" : "=r"(r) : "f"(x));
    return __uint_as_float(r);
}
__device__ __forceinline__ void atomicMaxFloat(float* addr, float v) {
    if (v >= 0.0f) atomicMax((int*)addr, __float_as_int(v));
    else           atomicMin((unsigned int*)addr, __float_as_uint(v));
}
__device__ __forceinline__ void cpa16(uint32_t d, const float* s) {
    asm volatile("cp.async.cg.shared.global [%0], [%1], 16;" :: "r"(d), "l"(s));
}
#define CP_COMMIT() asm volatile("cp.async.commit_group;" ::: "memory")
#define CP_WAIT0()  asm volatile("cp.async.wait_group 0;" ::: "memory")
#define CP_WAIT1()  asm volatile("cp.async.wait_group 1;" ::: "memory")

#define MMA8(d, a, b) \
    asm volatile("mma.sync.aligned.m16n8k8.row.col.f32.tf32.tf32.f32 " \
        "{%0,%1,%2,%3}, {%4,%5,%6,%7}, {%8,%9}, {%0,%1,%2,%3};" \
        : "+f"((d)[0]), "+f"((d)[1]), "+f"((d)[2]), "+f"((d)[3]) \
        : "r"((a)[0]), "r"((a)[1]), "r"((a)[2]), "r"((a)[3]), \
          "r"((b)[0]), "r"((b)[1]))

// load 128 rows x 32 cols (floats) row-major source into smem layout R
__device__ __forceinline__ void ldR4(uint32_t sb, const float* src, int ldg, int tid) {
    #pragma unroll
    for (int t = 0; t < 4; t++) {
        int idx = tid + t*256, r = idx >> 3, c = idx & 7;
        cpa16(sb + (uint32_t)(r*LDR + c*4)*4u, src + (size_t)r*ldg + c*4);
    }
}
// load 32 rows x 128 cols (floats) row-major source into smem layout T
__device__ __forceinline__ void ldT4(uint32_t sb, const float* src, int ldg, int tid) {
    #pragma unroll
    for (int t = 0; t < 4; t++) {
        int idx = tid + t*256, r = idx >> 5, c = idx & 31;
        cpa16(sb + (uint32_t)(r*LDT + c*4)*4u, src + (size_t)r*ldg + c*4);
    }
}

// 64x32 warp tile over one KC=32 chunk; smem layout R ([row][k], ld 36)
__device__ __forceinline__ void coreR(const float* As, const float* Bs,
                                      float acc[4][4][4], int wm, int wn, int gid, int tig) {
    #pragma unroll
    for (int k8 = 0; k8 < 32; k8 += 8) {
        uint32_t a[4][4], b[4][2];
        #pragma unroll
        for (int im = 0; im < 4; im++) {
            int rb = wm + im*16;
            a[im][0] = __float_as_uint(As[(rb+gid  )*LDR + k8+tig  ]);
            a[im][1] = __float_as_uint(As[(rb+gid+8)*LDR + k8+tig  ]);
            a[im][2] = __float_as_uint(As[(rb+gid  )*LDR + k8+tig+4]);
            a[im][3] = __float_as_uint(As[(rb+gid+8)*LDR + k8+tig+4]);
        }
        #pragma unroll
        for (int jn = 0; jn < 4; jn++) {
            int nb = wn + jn*8;
            b[jn][0] = __float_as_uint(Bs[(nb+gid)*LDR + k8+tig  ]);
            b[jn][1] = __float_as_uint(Bs[(nb+gid)*LDR + k8+tig+4]);
        }
        #pragma unroll
        for (int im = 0; im < 4; im++)
            #pragma unroll
            for (int jn = 0; jn < 4; jn++)
                MMA8(acc[im][jn], a[im], b[jn]);
    }
}
// same but smem layout T ([k][row], ld 136)
__device__ __forceinline__ void coreT(const float* As, const float* Bs,
                                      float acc[4][4][4], int wm, int wn, int gid, int tig) {
    #pragma unroll
    for (int k8 = 0; k8 < 32; k8 += 8) {
        uint32_t a[4][4], b[4][2];
        #pragma unroll
        for (int im = 0; im < 4; im++) {
            int rb = wm + im*16;
            a[im][0] = __float_as_uint(As[(k8+tig  )*LDT + rb+gid  ]);
            a[im][1] = __float_as_uint(As[(k8+tig  )*LDT + rb+gid+8]);
            a[im][2] = __float_as_uint(As[(k8+tig+4)*LDT + rb+gid  ]);
            a[im][3] = __float_as_uint(As[(k8+tig+4)*LDT + rb+gid+8]);
        }
        #pragma unroll
        for (int jn = 0; jn < 4; jn++) {
            int nb = wn + jn*8;
            b[jn][0] = __float_as_uint(Bs[(k8+tig  )*LDT + nb+gid]);
            b[jn][1] = __float_as_uint(Bs[(k8+tig+4)*LDT + nb+gid]);
        }
        #pragma unroll
        for (int im = 0; im < 4; im++)
            #pragma unroll
            for (int jn = 0; jn < 4; jn++)
                MMA8(acc[im][jn], a[im], b[jn]);
    }
}

// ---------------- prep kernels ------------------------------------------------
__global__ __launch_bounds__(256) void k_prep_w(
    const float* __restrict__ Wq, const float* __restrict__ Wk, const float* __restrict__ Wv) {
    int idx = blockIdx.x * 256 + threadIdx.x;          // 0..393215
    int row = idx >> 10, k = idx & 1023;
    const float* W = (row < 128) ? Wq : (row < 256) ? Wk : Wv;
    int n = row & 127;
    float v = W[(size_t)k * DKK + n];
    float h = rndtf(v);
    g_Wh[idx] = h;
    g_Wl[idx] = rndtf(v - h);
}
__global__ __launch_bounds__(256) void k_prep_om(const float* __restrict__ om) {
    int idx = blockIdx.x * 256 + threadIdx.x;          // 0..32767
    float v = om[idx];
    float h = rndtf(v);
    g_omh[idx] = h;
    g_oml[idx] = rndtf(v - h);
}
__global__ void k0_init() {
    int tid = blockIdx.x * blockDim.x + threadIdx.x;
    int nt  = gridDim.x * blockDim.x;
    if (tid == 0) g_gkmax = __int_as_float(0xff800000);
    for (int i = tid; i < BB*DVV*MM; i += nt) g_kvT[i] = 0.0f;
    for (int i = tid; i < BB*MM;     i += nt) g_ksum[i] = 0.0f;
}

// split one 128x32 raw-x tile into Ah (and optionally Al) in smem
template<bool LO>
__device__ __forceinline__ void split_tile(const float* Xr, float* Ahp, float* Alp, int tid) {
    int r = tid >> 1, c0 = (tid & 1) * 16;
    #pragma unroll
    for (int j = 0; j < 4; j++) {
        float4 v = *(const float4*)&Xr[r*LDR + c0 + j*4];
        float4 h, l;
        h.x = rndtf(v.x); h.y = rndtf(v.y); h.z = rndtf(v.z); h.w = rndtf(v.w);
        *(float4*)&Ahp[r*LDR + c0 + j*4] = h;
        if (LO) {
            l.x = rndtf(v.x - h.x); l.y = rndtf(v.y - h.y);
            l.z = rndtf(v.z - h.z); l.w = rndtf(v.w - h.w);
            *(float4*)&Alp[r*LDR + c0 + j*4] = l;
        }
    }
}

// ---------------- K1a: q+k GEMM, 3xTF32, x split in smem ----------------------
__global__ __launch_bounds__(256,1) void k1_qk(
    const float* __restrict__ x, const float* __restrict__ bq, const float* __restrict__ bk) {
    extern __shared__ char smarr[];
    uint32_t sb = smem_u32(smarr);
    const int tid = threadIdx.x, lane = tid & 31, wid = tid >> 5;
    const int gid = lane >> 2, tig = lane & 3;
    const int wm = (wid >> 2)*64, wn = (wid & 3)*32;
    const int row0 = blockIdx.x * 128;
    const float* X = x + (size_t)row0*DD;
    float* Ahp = (float*)(smarr + 2*QK_STG);
    float* Alp = Ahp + TILE_F;
    float accq[4][4][4] = {}, acck[4][4][4] = {};

    // chunk stage layout: Xr@0, Bqh@T, Bql@2T, Bkh@3T, Bkl@4T
    {
        ldR4(sb, X, DD, tid);
        ldR4(sb +   TILE_B, g_Wh, DD, tid);
        ldR4(sb + 2*TILE_B, g_Wl, DD, tid);
        ldR4(sb + 3*TILE_B, g_Wh + (size_t)128*DD, DD, tid);
        ldR4(sb + 4*TILE_B, g_Wl + (size_t)128*DD, DD, tid);
        CP_COMMIT();
    }
    for (int c = 0; c < 32; c++) {
        CP_WAIT0();
        __syncthreads();                     // data(c) ready; coreR(c-1) done
        if (c+1 < 32) {
            uint32_t st = sb + ((c+1)&1)*QK_STG;
            const float* Xn = X + (c+1)*32;
            ldR4(st, Xn, DD, tid);
            ldR4(st +   TILE_B, g_Wh + (c+1)*32, DD, tid);
            ldR4(st + 2*TILE_B, g_Wl + (c+1)*32, DD, tid);
            ldR4(st + 3*TILE_B, g_Wh + (size_t)128*DD + (c+1)*32, DD, tid);
            ldR4(st + 4*TILE_B, g_Wl + (size_t)128*DD + (c+1)*32, DD, tid);
            CP_COMMIT();
        }
        const float* S = (const float*)(smarr + (c&1)*QK_STG);
        split_tile<true>(S, Ahp, Alp, tid);
        __syncthreads();                     // Ah/Al ready
        coreR(Ahp, S +   TILE_F, accq, wm, wn, gid, tig);   // Ah*Bqh
        coreR(Ahp, S + 2*TILE_F, accq, wm, wn, gid, tig);   // Ah*Bql
        coreR(Alp, S +   TILE_F, accq, wm, wn, gid, tig);   // Al*Bqh
        coreR(Ahp, S + 3*TILE_F, acck, wm, wn, gid, tig);
        coreR(Ahp, S + 4*TILE_F, acck, wm, wn, gid, tig);
        coreR(Alp, S + 3*TILE_F, acck, wm, wn, gid, tig);
    }
    const float QKS = 0.29730177875068026f;   // 128^-0.25
    #pragma unroll
    for (int w2 = 0; w2 < 2; w2++) {
        float (*acc)[4][4] = w2 ? acck : accq;
        const float* bias  = w2 ? bk : bq;
        float* oh = w2 ? g_kh : g_qh;
        float* ol = w2 ? g_kl : g_ql;
        #pragma unroll
        for (int im = 0; im < 4; im++) {
            #pragma unroll
            for (int jn = 0; jn < 4; jn++) {
                int row = row0 + wm + im*16 + gid;
                int col = wn + jn*8 + tig*2;
                float b0 = bias[col], b1 = bias[col+1];
                #pragma unroll
                for (int half = 0; half < 2; half++) {
                    float f0 = (acc[im][jn][half*2+0] + b0)*QKS;
                    float f1 = (acc[im][jn][half*2+1] + b1)*QKS;
                    size_t off = (size_t)(row + half*8)*128 + col;
                    float2 h, l;
                    h.x = rndtf(f0); h.y = rndtf(f1);
                    *(float2*)(oh + off) = h;
                    l.x = rndtf(f0 - h.x); l.y = rndtf(f1 - h.y);
                    *(float2*)(ol + off) = l;
                }
            }
        }
    }
}

// ---------------- K1c: v GEMM, single tf32, x split (hi only) in smem ---------
__global__ __launch_bounds__(256,1) void k1_v(
    const float* __restrict__ x, const float* __restrict__ bv) {
    extern __shared__ char smarr[];
    uint32_t sb = smem_u32(smarr);
    const int tid = threadIdx.x, lane = tid & 31, wid = tid >> 5;
    const int gid = lane >> 2, tig = lane & 3;
    const int wm = (wid >> 2)*64, wn = (wid & 3)*32;
    const int row0 = blockIdx.x * 128;
    const float* X = x + (size_t)row0*DD;
    const float* Wv = g_Wh + (size_t)256*DD;
    float* Ahp = (float*)(smarr + 2*V_STG);
    float acc[4][4][4] = {};

    { ldR4(sb, X, DD, tid); ldR4(sb + TILE_B, Wv, DD, tid); CP_COMMIT(); }
    for (int c = 0; c < 32; c++) {
        CP_WAIT0();
        __syncthreads();
        if (c+1 < 32) {
            uint32_t st = sb + ((c+1)&1)*V_STG;
            ldR4(st, X + (c+1)*32, DD, tid);
            ldR4(st + TILE_B, Wv + (c+1)*32, DD, tid);
            CP_COMMIT();
        }
        const float* S = (const float*)(smarr + (c&1)*V_STG);
        split_tile<false>(S, Ahp, Ahp, tid);
        __syncthreads();
        coreR(Ahp, S + TILE_F, acc, wm, wn, gid, tig);
    }
    #pragma unroll
    for (int im = 0; im < 4; im++) {
        #pragma unroll
        for (int jn = 0; jn < 4; jn++) {
            int row = row0 + wm + im*16 + gid;
            int col = wn + jn*8 + tig*2;
            float b0 = bv[col], b1 = bv[col+1];
            float2 v;
            v.x = rndtf(acc[im][jn][0] + b0); v.y = rndtf(acc[im][jn][1] + b1);
            *(float2*)(g_vr + (size_t)row*128 + col) = v;
            v.x = rndtf(acc[im][jn][2] + b0); v.y = rndtf(acc[im][jn][3] + b1);
            *(float2*)(g_vr + (size_t)(row+8)*128 + col) = v;
        }
    }
}

// ---------------- K1b: row norms of full q, k (hi+lo) -------------------------
__global__ __launch_bounds__(256) void k1b_norms() {
    int t = blockIdx.x * 8 + (threadIdx.x >> 5);
    int lane = threadIdx.x & 31;
    {
        float4 h = ((const float4*)(g_qh + (size_t)t*DKK))[lane];
        float4 l = ((const float4*)(g_ql + (size_t)t*DKK))[lane];
        float ax = h.x+l.x, ay = h.y+l.y, az = h.z+l.z, aw = h.w+l.w;
        float s = ax*ax + ay*ay + az*az + aw*aw;
        #pragma unroll
        for (int o = 16; o; o >>= 1) s += __shfl_xor_sync(0xffffffffu, s, o);
        if (lane == 0) g_qn[t] = s;
    }
    {
        float4 h = ((const float4*)(g_kh + (size_t)t*DKK))[lane];
        float4 l = ((const float4*)(g_kl + (size_t)t*DKK))[lane];
        float ax = h.x+l.x, ay = h.y+l.y, az = h.z+l.z, aw = h.w+l.w;
        float s = ax*ax + ay*ay + az*az + aw*aw;
        #pragma unroll
        for (int o = 16; o; o >>= 1) s += __shfl_xor_sync(0xffffffffu, s, o);
        if (lane == 0) g_kn[t] = s;
    }
}

// ---------------- K2: feature projection, 3xTF32, both n0 halves --------------
__global__ __launch_bounds__(256,1) void k2_mma() {
    extern __shared__ char smarr[];
    uint32_t sb = smem_u32(smarr);
    const int tid = threadIdx.x, lane = tid & 31, wid = tid >> 5;
    const int gid = lane >> 2, tig = lane & 3;
    const int wm = (wid >> 2)*64, wn = (wid & 3)*32;
    const int row0 = blockIdx.x * 128;
    const bool isK = blockIdx.y != 0;
    const float* Ah = (isK ? g_kh : g_qh) + (size_t)row0*DKK;
    const float* Al = (isK ? g_kl : g_ql) + (size_t)row0*DKK;
    const float* nrm  = isK ? g_kn : g_qn;
    float* out        = isK ? g_pk : g_pq;
    float acc[2][4][4][4] = {};

    // stage: Ah@0, Al@T, Bh0@2T, Bl0@3T, Bh1@4T, Bl1@5T
    {
        ldR4(sb,            Ah, DKK, tid);
        ldR4(sb +   TILE_B, Al, DKK, tid);
        ldR4(sb + 2*TILE_B, g_omh, DKK, tid);
        ldR4(sb + 3*TILE_B, g_oml, DKK, tid);
        ldR4(sb + 4*TILE_B, g_omh + 128*DKK, DKK, tid);
        ldR4(sb + 5*TILE_B, g_oml + 128*DKK, DKK, tid);
        CP_COMMIT();
    }
    for (int c = 0; c < 4; c++) {
        if (c+1 < 4) {
            uint32_t st = sb + ((c+1)&1)*K2_STG;
            ldR4(st,            Ah + (c+1)*32, DKK, tid);
            ldR4(st +   TILE_B, Al + (c+1)*32, DKK, tid);
            ldR4(st + 2*TILE_B, g_omh + (c+1)*32, DKK, tid);
            ldR4(st + 3*TILE_B, g_oml + (c+1)*32, DKK, tid);
            ldR4(st + 4*TILE_B, g_omh + 128*DKK + (c+1)*32, DKK, tid);
            ldR4(st + 5*TILE_B, g_oml + 128*DKK + (c+1)*32, DKK, tid);
            CP_COMMIT();
            CP_WAIT1();
        } else {
            CP_WAIT0();
        }
        __syncthreads();
        const float* S = (const float*)(smarr + (c&1)*K2_STG);
        #pragma unroll
        for (int h = 0; h < 2; h++) {
            coreR(S,          S + (2+2*h)*TILE_F, acc[h], wm, wn, gid, tig);  // Ah*Bh
            coreR(S,          S + (3+2*h)*TILE_F, acc[h], wm, wn, gid, tig);  // Ah*Bl
            coreR(S + TILE_F, S + (2+2*h)*TILE_F, acc[h], wm, wn, gid, tig);  // Al*Bh
        }
        __syncthreads();
    }
    #pragma unroll
    for (int h = 0; h < 2; h++) {
        #pragma unroll
        for (int im = 0; im < 4; im++) {
            #pragma unroll
            for (int jn = 0; jn < 4; jn++) {
                int row = row0 + wm + im*16 + gid;
                int col = h*128 + wn + jn*8 + tig*2;
                float hn0 = 0.5f * nrm[row], hn1 = 0.5f * nrm[row+8];
                float2 v;
                v.x = acc[h][im][jn][0] - hn0; v.y = acc[h][im][jn][1] - hn0;
                *(float2*)(out + (size_t)row*MM + col) = v;
                v.x = acc[h][im][jn][2] - hn1; v.y = acc[h][im][jn][3] - hn1;
                *(float2*)(out + (size_t)(row+8)*MM + col) = v;
            }
        }
    }
}

// ---------------- K3a: phi_q = rnd(exp(pq - rowmax)/16); pk global max --------
__global__ __launch_bounds__(256) void k3a() {
    __shared__ float wmax[8];
    int t = blockIdx.x * 8 + (threadIdx.x >> 5);
    int lane = threadIdx.x & 31;
    float* pq = g_pq + (size_t)t*MM;
    float4 v0 = *(float4*)(pq + lane*4);
    float4 v1 = *(float4*)(pq + 128 + lane*4);
    float mx = fmaxf(fmaxf(fmaxf(v0.x, v0.y), fmaxf(v0.z, v0.w)),
                     fmaxf(fmaxf(v1.x, v1.y), fmaxf(v1.z, v1.w)));
    #pragma unroll
    for (int o = 16; o; o >>= 1) mx = fmaxf(mx, __shfl_xor_sync(0xffffffffu, mx, o));
    float4 e0, e1;
    e0.x = rndtf(expf(v0.x - mx)*0.0625f); e0.y = rndtf(expf(v0.y - mx)*0.0625f);
    e0.z = rndtf(expf(v0.z - mx)*0.0625f); e0.w = rndtf(expf(v0.w - mx)*0.0625f);
    e1.x = rndtf(expf(v1.x - mx)*0.0625f); e1.y = rndtf(expf(v1.y - mx)*0.0625f);
    e1.z = rndtf(expf(v1.z - mx)*0.0625f); e1.w = rndtf(expf(v1.w - mx)*0.0625f);
    *(float4*)(pq + lane*4) = e0;
    *(float4*)(pq + 128 + lane*4) = e1;
    const float* pk = g_pk + (size_t)t*MM;
    float4 k0 = *(const float4*)(pk + lane*4);
    float4 k1 = *(const float4*)(pk + 128 + lane*4);
    float km = fmaxf(fmaxf(fmaxf(k0.x, k0.y), fmaxf(k0.z, k0.w)),
                     fmaxf(fmaxf(k1.x, k1.y), fmaxf(k1.z, k1.w)));
    #pragma unroll
    for (int o = 16; o; o >>= 1) km = fmaxf(km, __shfl_xor_sync(0xffffffffu, km, o));
    if (lane == 0) wmax[threadIdx.x >> 5] = km;
    __syncthreads();
    if (threadIdx.x == 0) {
        float bm = wmax[0];
        #pragma unroll
        for (int w = 1; w < 8; w++) bm = fmaxf(bm, wmax[w]);
        atomicMaxFloat(&g_gkmax, bm);
    }
}

// ---------------- K3b: phi_k = rnd(exp(pk - gmax)/16) -------------------------
__global__ __launch_bounds__(256) void k3b() {
    float gm = g_gkmax;
    size_t n4 = (size_t)TT*MM/4;
    size_t stride = (size_t)gridDim.x * blockDim.x;
    for (size_t i = (size_t)blockIdx.x*blockDim.x + threadIdx.x; i < n4; i += stride) {
        float4 v = ((float4*)g_pk)[i];
        v.x = rndtf(expf(v.x - gm)*0.0625f); v.y = rndtf(expf(v.y - gm)*0.0625f);
        v.z = rndtf(expf(v.z - gm)*0.0625f); v.w = rndtf(expf(v.w - gm)*0.0625f);
        ((float4*)g_pk)[i] = v;
    }
}

// ---------------- K4: kvT[b][d][m] += sum_s phi_k[s][m] v[s][d] ---------------
__global__ __launch_bounds__(256,2) void k4_mma() {
    extern __shared__ char smarr[];
    uint32_t sb = smem_u32(smarr);
    const int tid = threadIdx.x, lane = tid & 31, wid = tid >> 5;
    const int gid = lane >> 2, tig = lane & 3;
    const int wm = (wid >> 2)*64, wn = (wid & 3)*32;
    const int b = blockIdx.x, m0 = blockIdx.y * 128, sp = blockIdx.z;
    const float* Asrc = g_pk + ((size_t)b*SS + sp*512)*MM + m0;   // rows=s, cols=m
    const float* Bsrc = g_vr + ((size_t)b*SS + sp*512)*DVV;       // rows=s, cols=d
    float acc[4][4][4] = {};

    { ldT4(sb, Asrc, MM, tid); ldT4(sb + TILE_B, Bsrc, DVV, tid); CP_COMMIT(); }
    for (int c = 0; c < 16; c++) {
        if (c+1 < 16) {
            uint32_t st = sb + ((c+1)&1)*STG2_B;
            ldT4(st, Asrc + (size_t)(c+1)*32*MM, MM, tid);
            ldT4(st + TILE_B, Bsrc + (size_t)(c+1)*32*DVV, DVV, tid);
            CP_COMMIT();
            CP_WAIT1();
        } else {
            CP_WAIT0();
        }
        __syncthreads();
        const float* S = (const float*)(smarr + (c&1)*STG2_B);
        coreT(S, S + TILE_F, acc, wm, wn, gid, tig);
        __syncthreads();
    }
    float* kvb = g_kvT + (size_t)b*DVV*MM;
    #pragma unroll
    for (int im = 0; im < 4; im++) {
        #pragma unroll
        for (int jn = 0; jn < 4; jn++) {
            int m = m0 + wm + im*16 + gid;
            int d = wn + jn*8 + tig*2;
            atomicAdd(&kvb[(size_t)d*MM + m],       acc[im][jn][0]);
            atomicAdd(&kvb[(size_t)(d+1)*MM + m],   acc[im][jn][1]);
            atomicAdd(&kvb[(size_t)d*MM + m+8],     acc[im][jn][2]);
            atomicAdd(&kvb[(size_t)(d+1)*MM + m+8], acc[im][jn][3]);
        }
    }
}

// ---------------- K4c: round kvT in place -------------------------------------
__global__ __launch_bounds__(256) void k4c_round() {
    int i = blockIdx.x * 256 + threadIdx.x;
    int n = BB*DVV*MM;
    for (; i < n; i += gridDim.x * 256) g_kvT[i] = rndtf(g_kvT[i]);
}

// ---------------- K4b: ksum[b,m] = sum_s phi_k --------------------------------
__global__ __launch_bounds__(256) void k4b_ksum() {
    int b = blockIdx.x, chunk = blockIdx.y, m = threadIdx.x;
    const float* Pk = g_pk + ((size_t)b*SS + chunk*128)*MM + m;
    float s = 0.0f;
    #pragma unroll 8
    for (int i = 0; i < 128; i++) s += Pk[(size_t)i*MM];
    atomicAdd(&g_ksum[b*MM + m], s);
}

// ---------------- K5a: den[t] = dot(phi_q[t], ksum[b]) + eps ------------------
__global__ __launch_bounds__(256) void k5a_den() {
    int t = blockIdx.x * 8 + (threadIdx.x >> 5);
    int lane = threadIdx.x & 31;
    int b = t >> 12;
    const float* pq = g_pq + (size_t)t*MM;
    const float* ks = g_ksum + b*MM;
    float4 p0 = *(const float4*)(pq + lane*4);
    float4 p1 = *(const float4*)(pq + 128 + lane*4);
    float4 k0 = *(const float4*)(ks + lane*4);
    float4 k1 = *(const float4*)(ks + 128 + lane*4);
    float s = p0.x*k0.x + p0.y*k0.y + p0.z*k0.z + p0.w*k0.w
            + p1.x*k1.x + p1.y*k1.y + p1.z*k1.z + p1.w*k1.w;
    #pragma unroll
    for (int o = 16; o; o >>= 1) s += __shfl_xor_sync(0xffffffffu, s, o);
    if (lane == 0) g_den[t] = s + EPSV;
}

// ---------------- K5: out = (phi_q @ kv) / den --------------------------------
__global__ __launch_bounds__(256,2) void k5_mma(float* __restrict__ out) {
    extern __shared__ char smarr[];
    uint32_t sb = smem_u32(smarr);
    const int tid = threadIdx.x, lane = tid & 31, wid = tid >> 5;
    const int gid = lane >> 2, tig = lane & 3;
    const int wm = (wid >> 2)*64, wn = (wid & 3)*32;
    const int row0 = blockIdx.x * 128;
    const int b = blockIdx.x >> 5;
    const float* Asrc = g_pq + (size_t)row0*MM;                 // rows=t, cols=m
    const float* Bsrc = g_kvT + (size_t)b*DVV*MM;               // rows=d, cols=m
    float acc[4][4][4] = {};

    { ldR4(sb, Asrc, MM, tid); ldR4(sb + TILE_B, Bsrc, MM, tid); CP_COMMIT(); }
    for (int c = 0; c < 8; c++) {
        if (c+1 < 8) {
            uint32_t st = sb + ((c+1)&1)*STG2_B;
            ldR4(st, Asrc + (c+1)*32, MM, tid);
            ldR4(st + TILE_B, Bsrc + (c+1)*32, MM, tid);
            CP_COMMIT();
            CP_WAIT1();
        } else {
            CP_WAIT0();
        }
        __syncthreads();
        const float* S = (const float*)(smarr + (c&1)*STG2_B);
        coreR(S, S + TILE_F, acc, wm, wn, gid, tig);
        __syncthreads();
    }
    #pragma unroll
    for (int im = 0; im < 4; im++) {
        #pragma unroll
        for (int jn = 0; jn < 4; jn++) {
            int row = row0 + wm + im*16 + gid;
            int col = wn + jn*8 + tig*2;
            float inv0 = 1.0f / g_den[row], inv1 = 1.0f / g_den[row+8];
            float2 v;
            v.x = acc[im][jn][0]*inv0; v.y = acc[im][jn][1]*inv0;
            *(float2*)(out + (size_t)row*DVV + col) = v;
            v.x = acc[im][jn][2]*inv1; v.y = acc[im][jn][3]*inv1;
            *(float2*)(out + (size_t)(row+8)*DVV + col) = v;
        }
    }
}

// ---------------- launch ------------------------------------------------------
extern "C" void kernel_launch(void* const* d_in, const int* in_sizes, int n_in,
                              void* d_out, int out_size) {
    const float* x     = (const float*)d_in[0];
    const float* Wq    = (const float*)d_in[1];
    const float* bq    = (const float*)d_in[2];
    const float* Wk    = (const float*)d_in[3];
    const float* bk    = (const float*)d_in[4];
    const float* Wv    = (const float*)d_in[5];
    const float* bv    = (const float*)d_in[6];
    const float* omega = (const float*)d_in[7];
    float* out = (float*)d_out;

    cudaFuncSetAttribute(k1_qk,  cudaFuncAttributeMaxDynamicSharedMemorySize, SMEM_QK);
    cudaFuncSetAttribute(k1_v,   cudaFuncAttributeMaxDynamicSharedMemorySize, SMEM_V);
    cudaFuncSetAttribute(k2_mma, cudaFuncAttributeMaxDynamicSharedMemorySize, SMEM_K2);
    cudaFuncSetAttribute(k4_mma, cudaFuncAttributeMaxDynamicSharedMemorySize, SMEM2);
    cudaFuncSetAttribute(k5_mma, cudaFuncAttributeMaxDynamicSharedMemorySize, SMEM2);

    k_prep_w<<<1536, 256>>>(Wq, Wk, Wv);
    k_prep_om<<<128, 256>>>(omega);
    k0_init<<<64, 256>>>();
    k1_qk<<<256, 256, SMEM_QK>>>(x, bq, bk);
    k1_v<<<256, 256, SMEM_V>>>(x, bv);
    k1b_norms<<<TT/8, 256>>>();
    k2_mma<<<dim3(256, 2), 256, SMEM_K2>>>();
    k3a<<<TT/8, 256>>>();
    k3b<<<2048, 256>>>();
    k4_mma<<<dim3(8, 2, 8), 256, SMEM2>>>();
    k4c_round<<<256, 256>>>();
    k4b_ksum<<<dim3(8, 32), 256>>>();
    k5a_den<<<TT/8, 256>>>();
    k5_mma<<<256, 256, SMEM2>>>(out);
}

// round 8
// speedup vs baseline: 2.5687x; 1.3994x over previous
#include <cuda_runtime.h>
#include <cuda_bf16.h>
#include <math.h>
#include <stdint.h>

#define BB 8
#define SS 4096
#define TT (BB*SS)          // 32768 tokens
#define DD 1024
#define DKK 128
#define DVV 128
#define MM 256
#define EPSV 1e-6f

#define LDR 36              // fp32 row-major smem leading dim (floats)
#define LDT 136             // fp32 k-major smem leading dim (floats)
#define LDB 40              // bf16 row-major smem leading dim (elements)
#define TILE_B 18432        // fp32 128x32 tile w/ pad, bytes
#define TILE_F 4608
#define BT_B 10240          // bf16 128x(32 pad 40) tile, bytes

#define QK_STG (TILE_B + 4*BT_B)          // Xraw + Bqh,Bqm,Bkh,Bkm = 59392
#define SMEM_QK (2*QK_STG + 2*BT_B)       // + Ah, Am = 139264
#define V_STG (2*TILE_B)
#define SMEM_V (2*V_STG + TILE_B)         // 92160
#define K2_STG (6*BT_B)                   // Ah, Am, Bh0, Bm0, Bh1, Bm1 = 61440
#define SMEM_K2 (2*K2_STG)                // 122880
#define STG2_B (2*TILE_B)
#define SMEM2 (2*STG2_B)                  // 73728 (k4, k5)

// ---------------- scratch (device globals; no allocation allowed) -------------
__device__ __align__(128) __nv_bfloat16 g_Wbh[256*DD];   // Wq|Wk transposed [n][k], hi
__device__ __align__(128) __nv_bfloat16 g_Wbm[256*DD];   // mid
__device__ float g_Wvf[128*DD];                          // Wv transposed, tf32-rounded
__device__ __align__(128) __nv_bfloat16 g_ombh[MM*DKK];
__device__ __align__(128) __nv_bfloat16 g_ombm[MM*DKK];
__device__ __align__(128) __nv_bfloat16 g_qbh[(size_t)TT*DKK];
__device__ __align__(128) __nv_bfloat16 g_qbm[(size_t)TT*DKK];
__device__ __align__(128) __nv_bfloat16 g_kbh[(size_t)TT*DKK];
__device__ __align__(128) __nv_bfloat16 g_kbm[(size_t)TT*DKK];
__device__ float g_vr[(size_t)TT*DVV];      // v, tf32-rounded
__device__ float g_pq[(size_t)TT*MM];       // logits, then phi_q (tf32-rounded)
__device__ float g_pk[(size_t)TT*MM];
__device__ float g_qn[TT];
__device__ float g_kn[TT];
__device__ float g_den[TT];
__device__ float g_kvT[BB*DVV*MM];          // kv transposed [b][d][m]
__device__ float g_ksum[BB*MM];
__device__ float g_gkmax;

// ---------------- helpers -----------------------------------------------------
__device__ __forceinline__ uint32_t smem_u32(const void* p) {
    uint32_t a;
    asm("{ .reg .u64 t; cvta.to.shared.u64 t, %1; cvt.u32.u64 %0, t; }" : "=r"(a) : "l"(p));
    return a;
}
__device__ __forceinline__ float rndtf(float x) {
    uint32_t r; asm("cvt.rna.tf32.f32 %0, %1;" : "=r"(r) : "f"(x));
    return __uint_as_float(r);
}
__device__ __forceinline__ void atomicMaxFloat(float* addr, float v) {
    if (v >= 0.0f) atomicMax((int*)addr, __float_as_int(v));
    else           atomicMin((unsigned int*)addr, __float_as_uint(v));
}
__device__ __forceinline__ void cpa16(uint32_t d, const void* s) {
    asm volatile("cp.async.cg.shared.global [%0], [%1], 16;" :: "r"(d), "l"(s));
}
#define CP_COMMIT() asm volatile("cp.async.commit_group;" ::: "memory")
#define CP_WAIT0()  asm volatile("cp.async.wait_group 0;" ::: "memory")
#define CP_WAIT1()  asm volatile("cp.async.wait_group 1;" ::: "memory")

#define MMA8(d, a, b) \
    asm volatile("mma.sync.aligned.m16n8k8.row.col.f32.tf32.tf32.f32 " \
        "{%0,%1,%2,%3}, {%4,%5,%6,%7}, {%8,%9}, {%0,%1,%2,%3};" \
        : "+f"((d)[0]), "+f"((d)[1]), "+f"((d)[2]), "+f"((d)[3]) \
        : "r"((a)[0]), "r"((a)[1]), "r"((a)[2]), "r"((a)[3]), \
          "r"((b)[0]), "r"((b)[1]))

#define MMA16(d, a, b) \
    asm volatile("mma.sync.aligned.m16n8k16.row.col.f32.bf16.bf16.f32 " \
        "{%0,%1,%2,%3}, {%4,%5,%6,%7}, {%8,%9}, {%0,%1,%2,%3};" \
        : "+f"((d)[0]), "+f"((d)[1]), "+f"((d)[2]), "+f"((d)[3]) \
        : "r"((a)[0]), "r"((a)[1]), "r"((a)[2]), "r"((a)[3]), \
          "r"((b)[0]), "r"((b)[1]))

// fp32 loaders (unchanged)
__device__ __forceinline__ void ldR4(uint32_t sb, const float* src, int ldg, int tid) {
    #pragma unroll
    for (int t = 0; t < 4; t++) {
        int idx = tid + t*256, r = idx >> 3, c = idx & 7;
        cpa16(sb + (uint32_t)(r*LDR + c*4)*4u, src + (size_t)r*ldg + c*4);
    }
}
__device__ __forceinline__ void ldT4(uint32_t sb, const float* src, int ldg, int tid) {
    #pragma unroll
    for (int t = 0; t < 4; t++) {
        int idx = tid + t*256, r = idx >> 5, c = idx & 31;
        cpa16(sb + (uint32_t)(r*LDT + c*4)*4u, src + (size_t)r*ldg + c*4);
    }
}
// bf16 tile loader: 128 rows x 32 elements (64B/row), into [row][LDB] bf16
__device__ __forceinline__ void ldB2(uint32_t sb, const __nv_bfloat16* src, int ldg, int tid) {
    #pragma unroll
    for (int t = 0; t < 2; t++) {
        int idx = tid + t*256, r = idx >> 2, c = idx & 3;
        cpa16(sb + (uint32_t)(r*(LDB*2) + c*16), src + (size_t)r*ldg + c*8);
    }
}

// 64x32 warp tile, fp32 tf32 mma, smem layout R ([row][k], ld 36)
__device__ __forceinline__ void coreR(const float* As, const float* Bs,
                                      float acc[4][4][4], int wm, int wn, int gid, int tig) {
    #pragma unroll
    for (int k8 = 0; k8 < 32; k8 += 8) {
        uint32_t a[4][4], b[4][2];
        #pragma unroll
        for (int im = 0; im < 4; im++) {
            int rb = wm + im*16;
            a[im][0] = __float_as_uint(As[(rb+gid  )*LDR + k8+tig  ]);
            a[im][1] = __float_as_uint(As[(rb+gid+8)*LDR + k8+tig  ]);
            a[im][2] = __float_as_uint(As[(rb+gid  )*LDR + k8+tig+4]);
            a[im][3] = __float_as_uint(As[(rb+gid+8)*LDR + k8+tig+4]);
        }
        #pragma unroll
        for (int jn = 0; jn < 4; jn++) {
            int nb = wn + jn*8;
            b[jn][0] = __float_as_uint(Bs[(nb+gid)*LDR + k8+tig  ]);
            b[jn][1] = __float_as_uint(Bs[(nb+gid)*LDR + k8+tig+4]);
        }
        #pragma unroll
        for (int im = 0; im < 4; im++)
            #pragma unroll
            for (int jn = 0; jn < 4; jn++)
                MMA8(acc[im][jn], a[im], b[jn]);
    }
}
// fp32 tf32 mma, smem layout T ([k][row], ld 136)
__device__ __forceinline__ void coreT(const float* As, const float* Bs,
                                      float acc[4][4][4], int wm, int wn, int gid, int tig) {
    #pragma unroll
    for (int k8 = 0; k8 < 32; k8 += 8) {
        uint32_t a[4][4], b[4][2];
        #pragma unroll
        for (int im = 0; im < 4; im++) {
            int rb = wm + im*16;
            a[im][0] = __float_as_uint(As[(k8+tig  )*LDT + rb+gid  ]);
            a[im][1] = __float_as_uint(As[(k8+tig  )*LDT + rb+gid+8]);
            a[im][2] = __float_as_uint(As[(k8+tig+4)*LDT + rb+gid  ]);
            a[im][3] = __float_as_uint(As[(k8+tig+4)*LDT + rb+gid+8]);
        }
        #pragma unroll
        for (int jn = 0; jn < 4; jn++) {
            int nb = wn + jn*8;
            b[jn][0] = __float_as_uint(Bs[(k8+tig  )*LDT + nb+gid]);
            b[jn][1] = __float_as_uint(Bs[(k8+tig+4)*LDT + nb+gid]);
        }
        #pragma unroll
        for (int im = 0; im < 4; im++)
            #pragma unroll
            for (int jn = 0; jn < 4; jn++)
                MMA8(acc[im][jn], a[im], b[jn]);
    }
}
// 64x32 warp tile, bf16 m16n8k16 mma, smem [row][k] bf16 ld LDB
__device__ __forceinline__ void coreRB(const __nv_bfloat16* As, const __nv_bfloat16* Bs,
                                       float acc[4][4][4], int wm, int wn, int gid, int tig) {
    #pragma unroll
    for (int k16 = 0; k16 < 32; k16 += 16) {
        uint32_t a[4][4], b[4][2];
        #pragma unroll
        for (int im = 0; im < 4; im++) {
            int rb = wm + im*16;
            a[im][0] = *(const uint32_t*)&As[(rb+gid  )*LDB + k16 + 2*tig];
            a[im][1] = *(const uint32_t*)&As[(rb+gid+8)*LDB + k16 + 2*tig];
            a[im][2] = *(const uint32_t*)&As[(rb+gid  )*LDB + k16 + 2*tig + 8];
            a[im][3] = *(const uint32_t*)&As[(rb+gid+8)*LDB + k16 + 2*tig + 8];
        }
        #pragma unroll
        for (int jn = 0; jn < 4; jn++) {
            int nb = wn + jn*8;
            b[jn][0] = *(const uint32_t*)&Bs[(nb+gid)*LDB + k16 + 2*tig];
            b[jn][1] = *(const uint32_t*)&Bs[(nb+gid)*LDB + k16 + 2*tig + 8];
        }
        #pragma unroll
        for (int im = 0; im < 4; im++)
            #pragma unroll
            for (int jn = 0; jn < 4; jn++)
                MMA16(acc[im][jn], a[im], b[jn]);
    }
}

// ---------------- prep kernels ------------------------------------------------
__global__ __launch_bounds__(256) void k_prep_w(
    const float* __restrict__ Wq, const float* __restrict__ Wk, const float* __restrict__ Wv) {
    int idx = blockIdx.x * 256 + threadIdx.x;          // 0..393215
    int row = idx >> 10, k = idx & 1023;
    if (row < 256) {
        const float* W = (row < 128) ? Wq : Wk;
        int n = row & 127;
        float v = W[(size_t)k * DKK + n];
        __nv_bfloat16 h = __float2bfloat16_rn(v);
        g_Wbh[idx] = h;
        g_Wbm[idx] = __float2bfloat16_rn(v - __bfloat162float(h));
    } else {
        int n = row & 127;
        g_Wvf[(size_t)(row - 256)*DD + k] = rndtf(Wv[(size_t)k * DKK + n]);
    }
}
__global__ __launch_bounds__(256) void k_prep_om(const float* __restrict__ om) {
    int idx = blockIdx.x * 256 + threadIdx.x;          // 0..32767
    float v = om[idx];
    __nv_bfloat16 h = __float2bfloat16_rn(v);
    g_ombh[idx] = h;
    g_ombm[idx] = __float2bfloat16_rn(v - __bfloat162float(h));
}
__global__ void k0_init() {
    int tid = blockIdx.x * blockDim.x + threadIdx.x;
    int nt  = gridDim.x * blockDim.x;
    if (tid == 0) g_gkmax = __int_as_float(0xff800000);
    for (int i = tid; i < BB*DVV*MM; i += nt) g_kvT[i] = 0.0f;
    for (int i = tid; i < BB*MM;     i += nt) g_ksum[i] = 0.0f;
}

// split raw fp32 tile (layout R) -> bf16 hi/mid tiles (layout [r][LDB])
__device__ __forceinline__ void split_bf(const float* Xr, __nv_bfloat16* Hp,
                                         __nv_bfloat16* Mp, int tid) {
    int r = tid >> 1, c0 = (tid & 1) * 16;
    #pragma unroll
    for (int j = 0; j < 4; j++) {
        float4 v = *(const float4*)&Xr[r*LDR + c0 + j*4];
        __nv_bfloat16 hx = __float2bfloat16_rn(v.x);
        __nv_bfloat16 hy = __float2bfloat16_rn(v.y);
        __nv_bfloat16 hz = __float2bfloat16_rn(v.z);
        __nv_bfloat16 hw = __float2bfloat16_rn(v.w);
        *(__nv_bfloat162*)&Hp[r*LDB + c0 + j*4]     = __halves2bfloat162(hx, hy);
        *(__nv_bfloat162*)&Hp[r*LDB + c0 + j*4 + 2] = __halves2bfloat162(hz, hw);
        __nv_bfloat16 mx = __float2bfloat16_rn(v.x - __bfloat162float(hx));
        __nv_bfloat16 my = __float2bfloat16_rn(v.y - __bfloat162float(hy));
        __nv_bfloat16 mz = __float2bfloat16_rn(v.z - __bfloat162float(hz));
        __nv_bfloat16 mw = __float2bfloat16_rn(v.w - __bfloat162float(hw));
        *(__nv_bfloat162*)&Mp[r*LDB + c0 + j*4]     = __halves2bfloat162(mx, my);
        *(__nv_bfloat162*)&Mp[r*LDB + c0 + j*4 + 2] = __halves2bfloat162(mz, mw);
    }
}
// split hi-only to tf32 fp32 tile (for v path)
__device__ __forceinline__ void split_tf(const float* Xr, float* Ahp, int tid) {
    int r = tid >> 1, c0 = (tid & 1) * 16;
    #pragma unroll
    for (int j = 0; j < 4; j++) {
        float4 v = *(const float4*)&Xr[r*LDR + c0 + j*4];
        float4 h;
        h.x = rndtf(v.x); h.y = rndtf(v.y); h.z = rndtf(v.z); h.w = rndtf(v.w);
        *(float4*)&Ahp[r*LDR + c0 + j*4] = h;
    }
}

// ---------------- K1a: q+k GEMM, bf16 2-split 3-product -----------------------
__global__ __launch_bounds__(256,1) void k1_qk(
    const float* __restrict__ x, const float* __restrict__ bq, const float* __restrict__ bk) {
    extern __shared__ char smarr[];
    uint32_t sb = smem_u32(smarr);
    const int tid = threadIdx.x, lane = tid & 31, wid = tid >> 5;
    const int gid = lane >> 2, tig = lane & 3;
    const int wm = (wid >> 2)*64, wn = (wid & 3)*32;
    const int row0 = blockIdx.x * 128;
    const float* X = x + (size_t)row0*DD;
    const __nv_bfloat16* Wqh = g_Wbh;
    const __nv_bfloat16* Wqm = g_Wbm;
    const __nv_bfloat16* Wkh = g_Wbh + (size_t)128*DD;
    const __nv_bfloat16* Wkm = g_Wbm + (size_t)128*DD;
    __nv_bfloat16* Ahp = (__nv_bfloat16*)(smarr + 2*QK_STG);
    __nv_bfloat16* Amp = Ahp + BT_B/2;
    float accq[4][4][4] = {}, acck[4][4][4] = {};

    {   // prologue
        ldR4(sb, X, DD, tid);
        ldB2(sb + TILE_B,          Wqh, DD, tid);
        ldB2(sb + TILE_B + BT_B,   Wqm, DD, tid);
        ldB2(sb + TILE_B + 2*BT_B, Wkh, DD, tid);
        ldB2(sb + TILE_B + 3*BT_B, Wkm, DD, tid);
        CP_COMMIT();
    }
    for (int c = 0; c < 32; c++) {
        CP_WAIT0();
        __syncthreads();                     // data(c) ready; compute(c-1) done
        if (c+1 < 32) {
            uint32_t st = sb + ((c+1)&1)*QK_STG;
            const int o = (c+1)*32;
            ldR4(st, X + o, DD, tid);
            ldB2(st + TILE_B,          Wqh + o, DD, tid);
            ldB2(st + TILE_B + BT_B,   Wqm + o, DD, tid);
            ldB2(st + TILE_B + 2*BT_B, Wkh + o, DD, tid);
            ldB2(st + TILE_B + 3*BT_B, Wkm + o, DD, tid);
            CP_COMMIT();
        }
        const char* S = smarr + (c&1)*QK_STG;
        split_bf((const float*)S, Ahp, Amp, tid);
        __syncthreads();                     // Ah/Am ready
        const __nv_bfloat16* Bqh = (const __nv_bfloat16*)(S + TILE_B);
        const __nv_bfloat16* Bqm = (const __nv_bfloat16*)(S + TILE_B + BT_B);
        const __nv_bfloat16* Bkh = (const __nv_bfloat16*)(S + TILE_B + 2*BT_B);
        const __nv_bfloat16* Bkm = (const __nv_bfloat16*)(S + TILE_B + 3*BT_B);
        coreRB(Ahp, Bqh, accq, wm, wn, gid, tig);
        coreRB(Ahp, Bqm, accq, wm, wn, gid, tig);
        coreRB(Amp, Bqh, accq, wm, wn, gid, tig);
        coreRB(Ahp, Bkh, acck, wm, wn, gid, tig);
        coreRB(Ahp, Bkm, acck, wm, wn, gid, tig);
        coreRB(Amp, Bkh, acck, wm, wn, gid, tig);
    }
    const float QKS = 0.29730177875068026f;   // 128^-0.25
    #pragma unroll
    for (int w2 = 0; w2 < 2; w2++) {
        float (*acc)[4][4] = w2 ? acck : accq;
        const float* bias  = w2 ? bk : bq;
        __nv_bfloat16* oh = w2 ? g_kbh : g_qbh;
        __nv_bfloat16* om = w2 ? g_kbm : g_qbm;
        #pragma unroll
        for (int im = 0; im < 4; im++) {
            #pragma unroll
            for (int jn = 0; jn < 4; jn++) {
                int row = row0 + wm + im*16 + gid;
                int col = wn + jn*8 + tig*2;
                float b0 = bias[col], b1 = bias[col+1];
                #pragma unroll
                for (int half = 0; half < 2; half++) {
                    float f0 = (acc[im][jn][half*2+0] + b0)*QKS;
                    float f1 = (acc[im][jn][half*2+1] + b1)*QKS;
                    size_t off = (size_t)(row + half*8)*128 + col;
                    __nv_bfloat16 h0 = __float2bfloat16_rn(f0);
                    __nv_bfloat16 h1 = __float2bfloat16_rn(f1);
                    *(__nv_bfloat162*)(oh + off) = __halves2bfloat162(h0, h1);
                    __nv_bfloat16 m0 = __float2bfloat16_rn(f0 - __bfloat162float(h0));
                    __nv_bfloat16 m1 = __float2bfloat16_rn(f1 - __bfloat162float(h1));
                    *(__nv_bfloat162*)(om + off) = __halves2bfloat162(m0, m1);
                }
            }
        }
    }
}

// ---------------- K1c: v GEMM, single tf32 ------------------------------------
__global__ __launch_bounds__(256,1) void k1_v(
    const float* __restrict__ x, const float* __restrict__ bv) {
    extern __shared__ char smarr[];
    uint32_t sb = smem_u32(smarr);
    const int tid = threadIdx.x, lane = tid & 31, wid = tid >> 5;
    const int gid = lane >> 2, tig = lane & 3;
    const int wm = (wid >> 2)*64, wn = (wid & 3)*32;
    const int row0 = blockIdx.x * 128;
    const float* X = x + (size_t)row0*DD;
    float* Ahp = (float*)(smarr + 2*V_STG);
    float acc[4][4][4] = {};

    { ldR4(sb, X, DD, tid); ldR4(sb + TILE_B, g_Wvf, DD, tid); CP_COMMIT(); }
    for (int c = 0; c < 32; c++) {
        CP_WAIT0();
        __syncthreads();
        if (c+1 < 32) {
            uint32_t st = sb + ((c+1)&1)*V_STG;
            ldR4(st, X + (c+1)*32, DD, tid);
            ldR4(st + TILE_B, g_Wvf + (c+1)*32, DD, tid);
            CP_COMMIT();
        }
        const float* S = (const float*)(smarr + (c&1)*V_STG);
        split_tf(S, Ahp, tid);
        __syncthreads();
        coreR(Ahp, S + TILE_F, acc, wm, wn, gid, tig);
    }
    #pragma unroll
    for (int im = 0; im < 4; im++) {
        #pragma unroll
        for (int jn = 0; jn < 4; jn++) {
            int row = row0 + wm + im*16 + gid;
            int col = wn + jn*8 + tig*2;
            float b0 = bv[col], b1 = bv[col+1];
            float2 v;
            v.x = rndtf(acc[im][jn][0] + b0); v.y = rndtf(acc[im][jn][1] + b1);
            *(float2*)(g_vr + (size_t)row*128 + col) = v;
            v.x = rndtf(acc[im][jn][2] + b0); v.y = rndtf(acc[im][jn][3] + b1);
            *(float2*)(g_vr + (size_t)(row+8)*128 + col) = v;
        }
    }
}

// ---------------- K1b: row norms of q, k (h+m) --------------------------------
__global__ __launch_bounds__(256) void k1b_norms() {
    int t = blockIdx.x * 8 + (threadIdx.x >> 5);
    int lane = threadIdx.x & 31;
    #pragma unroll
    for (int w2 = 0; w2 < 2; w2++) {
        const __nv_bfloat16* bh = (w2 ? g_kbh : g_qbh) + (size_t)t*DKK;
        const __nv_bfloat16* bm = (w2 ? g_kbm : g_qbm) + (size_t)t*DKK;
        uint2 hw = ((const uint2*)bh)[lane];
        uint2 mw = ((const uint2*)bm)[lane];
        __nv_bfloat162 h01 = *(__nv_bfloat162*)&hw.x, h23 = *(__nv_bfloat162*)&hw.y;
        __nv_bfloat162 m01 = *(__nv_bfloat162*)&mw.x, m23 = *(__nv_bfloat162*)&mw.y;
        float a0 = __bfloat162float(h01.x) + __bfloat162float(m01.x);
        float a1 = __bfloat162float(h01.y) + __bfloat162float(m01.y);
        float a2 = __bfloat162float(h23.x) + __bfloat162float(m23.x);
        float a3 = __bfloat162float(h23.y) + __bfloat162float(m23.y);
        float s = a0*a0 + a1*a1 + a2*a2 + a3*a3;
        #pragma unroll
        for (int o = 16; o; o >>= 1) s += __shfl_xor_sync(0xffffffffu, s, o);
        if (lane == 0) (w2 ? g_kn : g_qn)[t] = s;
    }
}

// ---------------- K2: feature projection, bf16 2-split 3-product --------------
__global__ __launch_bounds__(256,1) void k2_mma() {
    extern __shared__ char smarr[];
    uint32_t sb = smem_u32(smarr);
    const int tid = threadIdx.x, lane = tid & 31, wid = tid >> 5;
    const int gid = lane >> 2, tig = lane & 3;
    const int wm = (wid >> 2)*64, wn = (wid & 3)*32;
    const int row0 = blockIdx.x * 128;
    const bool isK = blockIdx.y != 0;
    const __nv_bfloat16* Ah = (isK ? g_kbh : g_qbh) + (size_t)row0*DKK;
    const __nv_bfloat16* Am = (isK ? g_kbm : g_qbm) + (size_t)row0*DKK;
    const float* nrm  = isK ? g_kn : g_qn;
    float* out        = isK ? g_pk : g_pq;
    float acc[2][4][4][4] = {};

    // stage: Ah@0, Am@1, Bh0@2, Bm0@3, Bh1@4, Bm1@5 (x BT_B)
    {
        ldB2(sb,          Ah, DKK, tid);
        ldB2(sb +   BT_B, Am, DKK, tid);
        ldB2(sb + 2*BT_B, g_ombh, DKK, tid);
        ldB2(sb + 3*BT_B, g_ombm, DKK, tid);
        ldB2(sb + 4*BT_B, g_ombh + 128*DKK, DKK, tid);
        ldB2(sb + 5*BT_B, g_ombm + 128*DKK, DKK, tid);
        CP_COMMIT();
    }
    for (int c = 0; c < 4; c++) {
        if (c+1 < 4) {
            uint32_t st = sb + ((c+1)&1)*K2_STG;
            const int o = (c+1)*32;
            ldB2(st,          Ah + o, DKK, tid);
            ldB2(st +   BT_B, Am + o, DKK, tid);
            ldB2(st + 2*BT_B, g_ombh + o, DKK, tid);
            ldB2(st + 3*BT_B, g_ombm + o, DKK, tid);
            ldB2(st + 4*BT_B, g_ombh + 128*DKK + o, DKK, tid);
            ldB2(st + 5*BT_B, g_ombm + 128*DKK + o, DKK, tid);
            CP_COMMIT();
            CP_WAIT1();
        } else {
            CP_WAIT0();
        }
        __syncthreads();
        const char* S = smarr + (c&1)*K2_STG;
        const __nv_bfloat16* SAh = (const __nv_bfloat16*)S;
        const __nv_bfloat16* SAm = (const __nv_bfloat16*)(S + BT_B);
        #pragma unroll
        for (int h = 0; h < 2; h++) {
            const __nv_bfloat16* SBh = (const __nv_bfloat16*)(S + (2+2*h)*BT_B);
            const __nv_bfloat16* SBm = (const __nv_bfloat16*)(S + (3+2*h)*BT_B);
            coreRB(SAh, SBh, acc[h], wm, wn, gid, tig);
            coreRB(SAh, SBm, acc[h], wm, wn, gid, tig);
            coreRB(SAm, SBh, acc[h], wm, wn, gid, tig);
        }
        __syncthreads();
    }
    #pragma unroll
    for (int h = 0; h < 2; h++) {
        #pragma unroll
        for (int im = 0; im < 4; im++) {
            #pragma unroll
            for (int jn = 0; jn < 4; jn++) {
                int row = row0 + wm + im*16 + gid;
                int col = h*128 + wn + jn*8 + tig*2;
                float hn0 = 0.5f * nrm[row], hn1 = 0.5f * nrm[row+8];
                float2 v;
                v.x = acc[h][im][jn][0] - hn0; v.y = acc[h][im][jn][1] - hn0;
                *(float2*)(out + (size_t)row*MM + col) = v;
                v.x = acc[h][im][jn][2] - hn1; v.y = acc[h][im][jn][3] - hn1;
                *(float2*)(out + (size_t)(row+8)*MM + col) = v;
            }
        }
    }
}

// ---------------- K3a: phi_q = rnd(exp(pq - rowmax)/16); pk global max --------
__global__ __launch_bounds__(256) void k3a() {
    __shared__ float wmax[8];
    int t = blockIdx.x * 8 + (threadIdx.x >> 5);
    int lane = threadIdx.x & 31;
    float* pq = g_pq + (size_t)t*MM;
    float4 v0 = *(float4*)(pq + lane*4);
    float4 v1 = *(float4*)(pq + 128 + lane*4);
    float mx = fmaxf(fmaxf(fmaxf(v0.x, v0.y), fmaxf(v0.z, v0.w)),
                     fmaxf(fmaxf(v1.x, v1.y), fmaxf(v1.z, v1.w)));
    #pragma unroll
    for (int o = 16; o; o >>= 1) mx = fmaxf(mx, __shfl_xor_sync(0xffffffffu, mx, o));
    float4 e0, e1;
    e0.x = rndtf(expf(v0.x - mx)*0.0625f); e0.y = rndtf(expf(v0.y - mx)*0.0625f);
    e0.z = rndtf(expf(v0.z - mx)*0.0625f); e0.w = rndtf(expf(v0.w - mx)*0.0625f);
    e1.x = rndtf(expf(v1.x - mx)*0.0625f); e1.y = rndtf(expf(v1.y - mx)*0.0625f);
    e1.z = rndtf(expf(v1.z - mx)*0.0625f); e1.w = rndtf(expf(v1.w - mx)*0.0625f);
    *(float4*)(pq + lane*4) = e0;
    *(float4*)(pq + 128 + lane*4) = e1;
    const float* pk = g_pk + (size_t)t*MM;
    float4 k0 = *(const float4*)(pk + lane*4);
    float4 k1 = *(const float4*)(pk + 128 + lane*4);
    float km = fmaxf(fmaxf(fmaxf(k0.x, k0.y), fmaxf(k0.z, k0.w)),
                     fmaxf(fmaxf(k1.x, k1.y), fmaxf(k1.z, k1.w)));
    #pragma unroll
    for (int o = 16; o; o >>= 1) km = fmaxf(km, __shfl_xor_sync(0xffffffffu, km, o));
    if (lane == 0) wmax[threadIdx.x >> 5] = km;
    __syncthreads();
    if (threadIdx.x == 0) {
        float bm = wmax[0];
        #pragma unroll
        for (int w = 1; w < 8; w++) bm = fmaxf(bm, wmax[w]);
        atomicMaxFloat(&g_gkmax, bm);
    }
}

// ---------------- K3b: phi_k = rnd(exp(pk - gmax)/16) -------------------------
__global__ __launch_bounds__(256) void k3b() {
    float gm = g_gkmax;
    size_t n4 = (size_t)TT*MM/4;
    size_t stride = (size_t)gridDim.x * blockDim.x;
    for (size_t i = (size_t)blockIdx.x*blockDim.x + threadIdx.x; i < n4; i += stride) {
        float4 v = ((float4*)g_pk)[i];
        v.x = rndtf(expf(v.x - gm)*0.0625f); v.y = rndtf(expf(v.y - gm)*0.0625f);
        v.z = rndtf(expf(v.z - gm)*0.0625f); v.w = rndtf(expf(v.w - gm)*0.0625f);
        ((float4*)g_pk)[i] = v;
    }
}

// ---------------- K4: kvT[b][d][m] += sum_s phi_k[s][m] v[s][d] ---------------
__global__ __launch_bounds__(256,2) void k4_mma() {
    extern __shared__ char smarr[];
    uint32_t sb = smem_u32(smarr);
    const int tid = threadIdx.x, lane = tid & 31, wid = tid >> 5;
    const int gid = lane >> 2, tig = lane & 3;
    const int wm = (wid >> 2)*64, wn = (wid & 3)*32;
    const int b = blockIdx.x, m0 = blockIdx.y * 128, sp = blockIdx.z;
    const float* Asrc = g_pk + ((size_t)b*SS + sp*512)*MM + m0;
    const float* Bsrc = g_vr + ((size_t)b*SS + sp*512)*DVV;
    float acc[4][4][4] = {};

    { ldT4(sb, Asrc, MM, tid); ldT4(sb + TILE_B, Bsrc, DVV, tid); CP_COMMIT(); }
    for (int c = 0; c < 16; c++) {
        if (c+1 < 16) {
            uint32_t st = sb + ((c+1)&1)*STG2_B;
            ldT4(st, Asrc + (size_t)(c+1)*32*MM, MM, tid);
            ldT4(st + TILE_B, Bsrc + (size_t)(c+1)*32*DVV, DVV, tid);
            CP_COMMIT();
            CP_WAIT1();
        } else {
            CP_WAIT0();
        }
        __syncthreads();
        const float* S = (const float*)(smarr + (c&1)*STG2_B);
        coreT(S, S + TILE_F, acc, wm, wn, gid, tig);
        __syncthreads();
    }
    float* kvb = g_kvT + (size_t)b*DVV*MM;
    #pragma unroll
    for (int im = 0; im < 4; im++) {
        #pragma unroll
        for (int jn = 0; jn < 4; jn++) {
            int m = m0 + wm + im*16 + gid;
            int d = wn + jn*8 + tig*2;
            atomicAdd(&kvb[(size_t)d*MM + m],       acc[im][jn][0]);
            atomicAdd(&kvb[(size_t)(d+1)*MM + m],   acc[im][jn][1]);
            atomicAdd(&kvb[(size_t)d*MM + m+8],     acc[im][jn][2]);
            atomicAdd(&kvb[(size_t)(d+1)*MM + m+8], acc[im][jn][3]);
        }
    }
}

// ---------------- K4c: round kvT in place -------------------------------------
__global__ __launch_bounds__(256) void k4c_round() {
    int i = blockIdx.x * 256 + threadIdx.x;
    int n = BB*DVV*MM;
    for (; i < n; i += gridDim.x * 256) g_kvT[i] = rndtf(g_kvT[i]);
}

// ---------------- K4b: ksum[b,m] = sum_s phi_k --------------------------------
__global__ __launch_bounds__(256) void k4b_ksum() {
    int b = blockIdx.x, chunk = blockIdx.y, m = threadIdx.x;
    const float* Pk = g_pk + ((size_t)b*SS + chunk*128)*MM + m;
    float s = 0.0f;
    #pragma unroll 8
    for (int i = 0; i < 128; i++) s += Pk[(size_t)i*MM];
    atomicAdd(&g_ksum[b*MM + m], s);
}

// ---------------- K5a: den[t] = dot(phi_q[t], ksum[b]) + eps ------------------
__global__ __launch_bounds__(256) void k5a_den() {
    int t = blockIdx.x * 8 + (threadIdx.x >> 5);
    int lane = threadIdx.x & 31;
    int b = t >> 12;
    const float* pq = g_pq + (size_t)t*MM;
    const float* ks = g_ksum + b*MM;
    float4 p0 = *(const float4*)(pq + lane*4);
    float4 p1 = *(const float4*)(pq + 128 + lane*4);
    float4 k0 = *(const float4*)(ks + lane*4);
    float4 k1 = *(const float4*)(ks + 128 + lane*4);
    float s = p0.x*k0.x + p0.y*k0.y + p0.z*k0.z + p0.w*k0.w
            + p1.x*k1.x + p1.y*k1.y + p1.z*k1.z + p1.w*k1.w;
    #pragma unroll
    for (int o = 16; o; o >>= 1) s += __shfl_xor_sync(0xffffffffu, s, o);
    if (lane == 0) g_den[t] = s + EPSV;
}

// ---------------- K5: out = (phi_q @ kv) / den --------------------------------
__global__ __launch_bounds__(256,2) void k5_mma(float* __restrict__ out) {
    extern __shared__ char smarr[];
    uint32_t sb = smem_u32(smarr);
    const int tid = threadIdx.x, lane = tid & 31, wid = tid >> 5;
    const int gid = lane >> 2, tig = lane & 3;
    const int wm = (wid >> 2)*64, wn = (wid & 3)*32;
    const int row0 = blockIdx.x * 128;
    const int b = blockIdx.x >> 5;
    const float* Asrc = g_pq + (size_t)row0*MM;
    const float* Bsrc = g_kvT + (size_t)b*DVV*MM;
    float acc[4][4][4] = {};

    { ldR4(sb, Asrc, MM, tid); ldR4(sb + TILE_B, Bsrc, MM, tid); CP_COMMIT(); }
    for (int c = 0; c < 8; c++) {
        if (c+1 < 8) {
            uint32_t st = sb + ((c+1)&1)*STG2_B;
            ldR4(st, Asrc + (c+1)*32, MM, tid);
            ldR4(st + TILE_B, Bsrc + (c+1)*32, MM, tid);
            CP_COMMIT();
            CP_WAIT1();
        } else {
            CP_WAIT0();
        }
        __syncthreads();
        const float* S = (const float*)(smarr + (c&1)*STG2_B);
        coreR(S, S + TILE_F, acc, wm, wn, gid, tig);
        __syncthreads();
    }
    #pragma unroll
    for (int im = 0; im < 4; im++) {
        #pragma unroll
        for (int jn = 0; jn < 4; jn++) {
            int row = row0 + wm + im*16 + gid;
            int col = wn + jn*8 + tig*2;
            float inv0 = 1.0f / g_den[row], inv1 = 1.0f / g_den[row+8];
            float2 v;
            v.x = acc[im][jn][0]*inv0; v.y = acc[im][jn][1]*inv0;
            *(float2*)(out + (size_t)row*DVV + col) = v;
            v.x = acc[im][jn][2]*inv1; v.y = acc[im][jn][3]*inv1;
            *(float2*)(out + (size_t)(row+8)*DVV + col) = v;
        }
    }
}

// ---------------- launch ------------------------------------------------------
extern "C" void kernel_launch(void* const* d_in, const int* in_sizes, int n_in,
                              void* d_out, int out_size) {
    const float* x     = (const float*)d_in[0];
    const float* Wq    = (const float*)d_in[1];
    const float* bq    = (const float*)d_in[2];
    const float* Wk    = (const float*)d_in[3];
    const float* bk    = (const float*)d_in[4];
    const float* Wv    = (const float*)d_in[5];
    const float* bv    = (const float*)d_in[6];
    const float* omega = (const float*)d_in[7];
    float* out = (float*)d_out;

    cudaFuncSetAttribute(k1_qk,  cudaFuncAttributeMaxDynamicSharedMemorySize, SMEM_QK);
    cudaFuncSetAttribute(k1_v,   cudaFuncAttributeMaxDynamicSharedMemorySize, SMEM_V);
    cudaFuncSetAttribute(k2_mma, cudaFuncAttributeMaxDynamicSharedMemorySize, SMEM_K2);
    cudaFuncSetAttribute(k4_mma, cudaFuncAttributeMaxDynamicSharedMemorySize, SMEM2);
    cudaFuncSetAttribute(k5_mma, cudaFuncAttributeMaxDynamicSharedMemorySize, SMEM2);

    k_prep_w<<<1536, 256>>>(Wq, Wk, Wv);
    k_prep_om<<<128, 256>>>(omega);
    k0_init<<<64, 256>>>();
    k1_qk<<<256, 256, SMEM_QK>>>(x, bq, bk);
    k1_v<<<256, 256, SMEM_V>>>(x, bv);
    k1b_norms<<<TT/8, 256>>>();
    k2_mma<<<dim3(256, 2), 256, SMEM_K2>>>();
    k3a<<<TT/8, 256>>>();
    k3b<<<2048, 256>>>();
    k4_mma<<<dim3(8, 2, 8), 256, SMEM2>>>();
    k4c_round<<<256, 256>>>();
    k4b_ksum<<<dim3(8, 32), 256>>>();
    k5a_den<<<TT/8, 256>>>();
    k5_mma<<<256, 256, SMEM2>>>(out);
}

// round 9
// speedup vs baseline: 2.5797x; 1.0043x over previous
#include <cuda_runtime.h>
#include <cuda_bf16.h>
#include <math.h>
#include <stdint.h>

#define BB 8
#define SS 4096
#define TT (BB*SS)          // 32768 tokens
#define DD 1024
#define DKK 128
#define DVV 128
#define MM 256
#define EPSV 1e-6f

#define LDR 36              // fp32 row-major smem leading dim (floats)
#define LDT 136             // fp32 k-major smem leading dim (floats)
#define LDB 40              // bf16 row-major smem leading dim (elements)
#define TILE_B 18432        // fp32 128x32 tile w/ pad, bytes
#define TILE_F 4608
#define BT_B 10240          // bf16 128x(32 pad 40) tile, bytes

#define QK_STG (TILE_B + 2*BT_B)          // Xraw + Bh + Bm = 38912
#define SMEM_QK (2*QK_STG + 2*BT_B)       // + Ah, Am = 98304  (2 CTA/SM)
#define V_STG (2*TILE_B)
#define SMEM_V (2*V_STG + TILE_B)         // 92160 (2 CTA/SM)
#define K2_STG (4*BT_B)                   // Ah, Am, Bh, Bm = 40960
#define SMEM_K2 (2*K2_STG)                // 81920 (2 CTA/SM)
#define STG2_B (2*TILE_B)
#define SMEM2 (2*STG2_B)                  // 73728 (k4, k5)

// ---------------- scratch (device globals; no allocation allowed) -------------
__device__ __align__(128) __nv_bfloat16 g_Wbh[256*DD];   // Wq|Wk transposed [n][k], hi
__device__ __align__(128) __nv_bfloat16 g_Wbm[256*DD];   // mid
__device__ float g_Wvf[128*DD];                          // Wv transposed, tf32-rounded
__device__ __align__(128) __nv_bfloat16 g_ombh[MM*DKK];
__device__ __align__(128) __nv_bfloat16 g_ombm[MM*DKK];
__device__ __align__(128) __nv_bfloat16 g_qbh[(size_t)TT*DKK];
__device__ __align__(128) __nv_bfloat16 g_qbm[(size_t)TT*DKK];
__device__ __align__(128) __nv_bfloat16 g_kbh[(size_t)TT*DKK];
__device__ __align__(128) __nv_bfloat16 g_kbm[(size_t)TT*DKK];
__device__ float g_vr[(size_t)TT*DVV];      // v, tf32-rounded
__device__ float g_pq[(size_t)TT*MM];       // logits, then phi_q (tf32-rounded)
__device__ float g_pk[(size_t)TT*MM];
__device__ float g_qn[TT];
__device__ float g_kn[TT];
__device__ float g_den[TT];
__device__ float g_kvT[BB*DVV*MM];          // kv transposed [b][d][m]
__device__ float g_ksum[BB*MM];
__device__ float g_gkmax;

// ---------------- helpers -----------------------------------------------------
__device__ __forceinline__ uint32_t smem_u32(const void* p) {
    uint32_t a;
    asm("{ .reg .u64 t; cvta.to.shared.u64 t, %1; cvt.u32.u64 %0, t; }" : "=r"(a) : "l"(p));
    return a;
}
__device__ __forceinline__ float rndtf(float x) {
    uint32_t r; asm("cvt.rna.tf32.f32 %0, %1;" : "=r"(r) : "f"(x));
    return __uint_as_float(r);
}
__device__ __forceinline__ void atomicMaxFloat(float* addr, float v) {
    if (v >= 0.0f) atomicMax((int*)addr, __float_as_int(v));
    else           atomicMin((unsigned int*)addr, __float_as_uint(v));
}
__device__ __forceinline__ void cpa16(uint32_t d, const void* s) {
    asm volatile("cp.async.cg.shared.global [%0], [%1], 16;" :: "r"(d), "l"(s));
}
#define CP_COMMIT() asm volatile("cp.async.commit_group;" ::: "memory")
#define CP_WAIT0()  asm volatile("cp.async.wait_group 0;" ::: "memory")
#define CP_WAIT1()  asm volatile("cp.async.wait_group 1;" ::: "memory")

#define MMA8(d, a, b) \
    asm volatile("mma.sync.aligned.m16n8k8.row.col.f32.tf32.tf32.f32 " \
        "{%0,%1,%2,%3}, {%4,%5,%6,%7}, {%8,%9}, {%0,%1,%2,%3};" \
        : "+f"((d)[0]), "+f"((d)[1]), "+f"((d)[2]), "+f"((d)[3]) \
        : "r"((a)[0]), "r"((a)[1]), "r"((a)[2]), "r"((a)[3]), \
          "r"((b)[0]), "r"((b)[1]))

#define MMA16(d, a, b) \
    asm volatile("mma.sync.aligned.m16n8k16.row.col.f32.bf16.bf16.f32 " \
        "{%0,%1,%2,%3}, {%4,%5,%6,%7}, {%8,%9}, {%0,%1,%2,%3};" \
        : "+f"((d)[0]), "+f"((d)[1]), "+f"((d)[2]), "+f"((d)[3]) \
        : "r"((a)[0]), "r"((a)[1]), "r"((a)[2]), "r"((a)[3]), \
          "r"((b)[0]), "r"((b)[1]))

// fp32 loaders
__device__ __forceinline__ void ldR4(uint32_t sb, const float* src, int ldg, int tid) {
    #pragma unroll
    for (int t = 0; t < 4; t++) {
        int idx = tid + t*256, r = idx >> 3, c = idx & 7;
        cpa16(sb + (uint32_t)(r*LDR + c*4)*4u, src + (size_t)r*ldg + c*4);
    }
}
__device__ __forceinline__ void ldT4(uint32_t sb, const float* src, int ldg, int tid) {
    #pragma unroll
    for (int t = 0; t < 4; t++) {
        int idx = tid + t*256, r = idx >> 5, c = idx & 31;
        cpa16(sb + (uint32_t)(r*LDT + c*4)*4u, src + (size_t)r*ldg + c*4);
    }
}
// bf16 tile loader: 128 rows x 32 elements (64B/row), into [row][LDB] bf16
__device__ __forceinline__ void ldB2(uint32_t sb, const __nv_bfloat16* src, int ldg, int tid) {
    #pragma unroll
    for (int t = 0; t < 2; t++) {
        int idx = tid + t*256, r = idx >> 2, c = idx & 3;
        cpa16(sb + (uint32_t)(r*(LDB*2) + c*16), src + (size_t)r*ldg + c*8);
    }
}

// 64x32 warp tile, fp32 tf32 mma, smem layout R ([row][k], ld 36)
__device__ __forceinline__ void coreR(const float* As, const float* Bs,
                                      float acc[4][4][4], int wm, int wn, int gid, int tig) {
    #pragma unroll
    for (int k8 = 0; k8 < 32; k8 += 8) {
        uint32_t a[4][4], b[4][2];
        #pragma unroll
        for (int im = 0; im < 4; im++) {
            int rb = wm + im*16;
            a[im][0] = __float_as_uint(As[(rb+gid  )*LDR + k8+tig  ]);
            a[im][1] = __float_as_uint(As[(rb+gid+8)*LDR + k8+tig  ]);
            a[im][2] = __float_as_uint(As[(rb+gid  )*LDR + k8+tig+4]);
            a[im][3] = __float_as_uint(As[(rb+gid+8)*LDR + k8+tig+4]);
        }
        #pragma unroll
        for (int jn = 0; jn < 4; jn++) {
            int nb = wn + jn*8;
            b[jn][0] = __float_as_uint(Bs[(nb+gid)*LDR + k8+tig  ]);
            b[jn][1] = __float_as_uint(Bs[(nb+gid)*LDR + k8+tig+4]);
        }
        #pragma unroll
        for (int im = 0; im < 4; im++)
            #pragma unroll
            for (int jn = 0; jn < 4; jn++)
                MMA8(acc[im][jn], a[im], b[jn]);
    }
}
// fp32 tf32 mma, smem layout T ([k][row], ld 136)
__device__ __forceinline__ void coreT(const float* As, const float* Bs,
                                      float acc[4][4][4], int wm, int wn, int gid, int tig) {
    #pragma unroll
    for (int k8 = 0; k8 < 32; k8 += 8) {
        uint32_t a[4][4], b[4][2];
        #pragma unroll
        for (int im = 0; im < 4; im++) {
            int rb = wm + im*16;
            a[im][0] = __float_as_uint(As[(k8+tig  )*LDT + rb+gid  ]);
            a[im][1] = __float_as_uint(As[(k8+tig  )*LDT + rb+gid+8]);
            a[im][2] = __float_as_uint(As[(k8+tig+4)*LDT + rb+gid  ]);
            a[im][3] = __float_as_uint(As[(k8+tig+4)*LDT + rb+gid+8]);
        }
        #pragma unroll
        for (int jn = 0; jn < 4; jn++) {
            int nb = wn + jn*8;
            b[jn][0] = __float_as_uint(Bs[(k8+tig  )*LDT + nb+gid]);
            b[jn][1] = __float_as_uint(Bs[(k8+tig+4)*LDT + nb+gid]);
        }
        #pragma unroll
        for (int im = 0; im < 4; im++)
            #pragma unroll
            for (int jn = 0; jn < 4; jn++)
                MMA8(acc[im][jn], a[im], b[jn]);
    }
}
// 64x32 warp tile, bf16 m16n8k16 mma, smem [row][k] bf16 ld LDB
__device__ __forceinline__ void coreRB(const __nv_bfloat16* As, const __nv_bfloat16* Bs,
                                       float acc[4][4][4], int wm, int wn, int gid, int tig) {
    #pragma unroll
    for (int k16 = 0; k16 < 32; k16 += 16) {
        uint32_t a[4][4], b[4][2];
        #pragma unroll
        for (int im = 0; im < 4; im++) {
            int rb = wm + im*16;
            a[im][0] = *(const uint32_t*)&As[(rb+gid  )*LDB + k16 + 2*tig];
            a[im][1] = *(const uint32_t*)&As[(rb+gid+8)*LDB + k16 + 2*tig];
            a[im][2] = *(const uint32_t*)&As[(rb+gid  )*LDB + k16 + 2*tig + 8];
            a[im][3] = *(const uint32_t*)&As[(rb+gid+8)*LDB + k16 + 2*tig + 8];
        }
        #pragma unroll
        for (int jn = 0; jn < 4; jn++) {
            int nb = wn + jn*8;
            b[jn][0] = *(const uint32_t*)&Bs[(nb+gid)*LDB + k16 + 2*tig];
            b[jn][1] = *(const uint32_t*)&Bs[(nb+gid)*LDB + k16 + 2*tig + 8];
        }
        #pragma unroll
        for (int im = 0; im < 4; im++)
            #pragma unroll
            for (int jn = 0; jn < 4; jn++)
                MMA16(acc[im][jn], a[im], b[jn]);
    }
}

// ---------------- prep kernels ------------------------------------------------
__global__ __launch_bounds__(256) void k_prep_w(
    const float* __restrict__ Wq, const float* __restrict__ Wk, const float* __restrict__ Wv) {
    int idx = blockIdx.x * 256 + threadIdx.x;          // 0..393215
    int row = idx >> 10, k = idx & 1023;
    if (row < 256) {
        const float* W = (row < 128) ? Wq : Wk;
        int n = row & 127;
        float v = W[(size_t)k * DKK + n];
        __nv_bfloat16 h = __float2bfloat16_rn(v);
        g_Wbh[idx] = h;
        g_Wbm[idx] = __float2bfloat16_rn(v - __bfloat162float(h));
    } else {
        int n = row & 127;
        g_Wvf[(size_t)(row - 256)*DD + k] = rndtf(Wv[(size_t)k * DKK + n]);
    }
}
__global__ __launch_bounds__(256) void k_prep_om(const float* __restrict__ om) {
    int idx = blockIdx.x * 256 + threadIdx.x;          // 0..32767
    float v = om[idx];
    __nv_bfloat16 h = __float2bfloat16_rn(v);
    g_ombh[idx] = h;
    g_ombm[idx] = __float2bfloat16_rn(v - __bfloat162float(h));
}
__global__ void k0_init() {
    int tid = blockIdx.x * blockDim.x + threadIdx.x;
    int nt  = gridDim.x * blockDim.x;
    if (tid == 0) g_gkmax = __int_as_float(0xff800000);
    for (int i = tid; i < BB*DVV*MM; i += nt) g_kvT[i] = 0.0f;
    for (int i = tid; i < BB*MM;     i += nt) g_ksum[i] = 0.0f;
}

// split raw fp32 tile (layout R) -> bf16 hi/mid tiles (layout [r][LDB])
__device__ __forceinline__ void split_bf(const float* Xr, __nv_bfloat16* Hp,
                                         __nv_bfloat16* Mp, int tid) {
    int r = tid >> 1, c0 = (tid & 1) * 16;
    #pragma unroll
    for (int j = 0; j < 4; j++) {
        float4 v = *(const float4*)&Xr[r*LDR + c0 + j*4];
        __nv_bfloat16 hx = __float2bfloat16_rn(v.x);
        __nv_bfloat16 hy = __float2bfloat16_rn(v.y);
        __nv_bfloat16 hz = __float2bfloat16_rn(v.z);
        __nv_bfloat16 hw = __float2bfloat16_rn(v.w);
        *(__nv_bfloat162*)&Hp[r*LDB + c0 + j*4]     = __halves2bfloat162(hx, hy);
        *(__nv_bfloat162*)&Hp[r*LDB + c0 + j*4 + 2] = __halves2bfloat162(hz, hw);
        __nv_bfloat16 mx = __float2bfloat16_rn(v.x - __bfloat162float(hx));
        __nv_bfloat16 my = __float2bfloat16_rn(v.y - __bfloat162float(hy));
        __nv_bfloat16 mz = __float2bfloat16_rn(v.z - __bfloat162float(hz));
        __nv_bfloat16 mw = __float2bfloat16_rn(v.w - __bfloat162float(hw));
        *(__nv_bfloat162*)&Mp[r*LDB + c0 + j*4]     = __halves2bfloat162(mx, my);
        *(__nv_bfloat162*)&Mp[r*LDB + c0 + j*4 + 2] = __halves2bfloat162(mz, mw);
    }
}
// split hi-only to tf32 fp32 tile (for v path)
__device__ __forceinline__ void split_tf(const float* Xr, float* Ahp, int tid) {
    int r = tid >> 1, c0 = (tid & 1) * 16;
    #pragma unroll
    for (int j = 0; j < 4; j++) {
        float4 v = *(const float4*)&Xr[r*LDR + c0 + j*4];
        float4 h;
        h.x = rndtf(v.x); h.y = rndtf(v.y); h.z = rndtf(v.z); h.w = rndtf(v.w);
        *(float4*)&Ahp[r*LDR + c0 + j*4] = h;
    }
}

// ---------------- K1a: q or k GEMM (blockIdx.y), bf16 2-split 3-product -------
__global__ __launch_bounds__(256,2) void k1_qk(
    const float* __restrict__ x, const float* __restrict__ bq, const float* __restrict__ bk) {
    extern __shared__ char smarr[];
    uint32_t sb = smem_u32(smarr);
    const int tid = threadIdx.x, lane = tid & 31, wid = tid >> 5;
    const int gid = lane >> 2, tig = lane & 3;
    const int wm = (wid >> 2)*64, wn = (wid & 3)*32;
    const int row0 = blockIdx.x * 128;
    const int which = blockIdx.y;                       // 0=q, 1=k
    const float* X = x + (size_t)row0*DD;
    const __nv_bfloat16* Wh = g_Wbh + (size_t)which*128*DD;
    const __nv_bfloat16* Wm = g_Wbm + (size_t)which*128*DD;
    __nv_bfloat16* Ahp = (__nv_bfloat16*)(smarr + 2*QK_STG);
    __nv_bfloat16* Amp = Ahp + BT_B/2;
    float acc[4][4][4] = {};

    {   // prologue
        ldR4(sb, X, DD, tid);
        ldB2(sb + TILE_B,        Wh, DD, tid);
        ldB2(sb + TILE_B + BT_B, Wm, DD, tid);
        CP_COMMIT();
    }
    for (int c = 0; c < 32; c++) {
        CP_WAIT0();
        __syncthreads();                     // data(c) ready; compute(c-1) done
        if (c+1 < 32) {
            uint32_t st = sb + ((c+1)&1)*QK_STG;
            const int o = (c+1)*32;
            ldR4(st, X + o, DD, tid);
            ldB2(st + TILE_B,        Wh + o, DD, tid);
            ldB2(st + TILE_B + BT_B, Wm + o, DD, tid);
            CP_COMMIT();
        }
        const char* S = smarr + (c&1)*QK_STG;
        split_bf((const float*)S, Ahp, Amp, tid);
        __syncthreads();                     // Ah/Am ready
        const __nv_bfloat16* Bh = (const __nv_bfloat16*)(S + TILE_B);
        const __nv_bfloat16* Bm = (const __nv_bfloat16*)(S + TILE_B + BT_B);
        coreRB(Ahp, Bh, acc, wm, wn, gid, tig);
        coreRB(Ahp, Bm, acc, wm, wn, gid, tig);
        coreRB(Amp, Bh, acc, wm, wn, gid, tig);
    }
    const float QKS = 0.29730177875068026f;   // 128^-0.25
    const float* bias  = which ? bk : bq;
    __nv_bfloat16* oh = which ? g_kbh : g_qbh;
    __nv_bfloat16* om = which ? g_kbm : g_qbm;
    #pragma unroll
    for (int im = 0; im < 4; im++) {
        #pragma unroll
        for (int jn = 0; jn < 4; jn++) {
            int row = row0 + wm + im*16 + gid;
            int col = wn + jn*8 + tig*2;
            float b0 = bias[col], b1 = bias[col+1];
            #pragma unroll
            for (int half = 0; half < 2; half++) {
                float f0 = (acc[im][jn][half*2+0] + b0)*QKS;
                float f1 = (acc[im][jn][half*2+1] + b1)*QKS;
                size_t off = (size_t)(row + half*8)*128 + col;
                __nv_bfloat16 h0 = __float2bfloat16_rn(f0);
                __nv_bfloat16 h1 = __float2bfloat16_rn(f1);
                *(__nv_bfloat162*)(oh + off) = __halves2bfloat162(h0, h1);
                __nv_bfloat16 m0 = __float2bfloat16_rn(f0 - __bfloat162float(h0));
                __nv_bfloat16 m1 = __float2bfloat16_rn(f1 - __bfloat162float(h1));
                *(__nv_bfloat162*)(om + off) = __halves2bfloat162(m0, m1);
            }
        }
    }
}

// ---------------- K1c: v GEMM, single tf32 ------------------------------------
__global__ __launch_bounds__(256,2) void k1_v(
    const float* __restrict__ x, const float* __restrict__ bv) {
    extern __shared__ char smarr[];
    uint32_t sb = smem_u32(smarr);
    const int tid = threadIdx.x, lane = tid & 31, wid = tid >> 5;
    const int gid = lane >> 2, tig = lane & 3;
    const int wm = (wid >> 2)*64, wn = (wid & 3)*32;
    const int row0 = blockIdx.x * 128;
    const float* X = x + (size_t)row0*DD;
    float* Ahp = (float*)(smarr + 2*V_STG);
    float acc[4][4][4] = {};

    { ldR4(sb, X, DD, tid); ldR4(sb + TILE_B, g_Wvf, DD, tid); CP_COMMIT(); }
    for (int c = 0; c < 32; c++) {
        CP_WAIT0();
        __syncthreads();
        if (c+1 < 32) {
            uint32_t st = sb + ((c+1)&1)*V_STG;
            ldR4(st, X + (c+1)*32, DD, tid);
            ldR4(st + TILE_B, g_Wvf + (c+1)*32, DD, tid);
            CP_COMMIT();
        }
        const float* S = (const float*)(smarr + (c&1)*V_STG);
        split_tf(S, Ahp, tid);
        __syncthreads();
        coreR(Ahp, S + TILE_F, acc, wm, wn, gid, tig);
    }
    #pragma unroll
    for (int im = 0; im < 4; im++) {
        #pragma unroll
        for (int jn = 0; jn < 4; jn++) {
            int row = row0 + wm + im*16 + gid;
            int col = wn + jn*8 + tig*2;
            float b0 = bv[col], b1 = bv[col+1];
            float2 v;
            v.x = rndtf(acc[im][jn][0] + b0); v.y = rndtf(acc[im][jn][1] + b1);
            *(float2*)(g_vr + (size_t)row*128 + col) = v;
            v.x = rndtf(acc[im][jn][2] + b0); v.y = rndtf(acc[im][jn][3] + b1);
            *(float2*)(g_vr + (size_t)(row+8)*128 + col) = v;
        }
    }
}

// ---------------- K1b: row norms of q, k (h+m) --------------------------------
__global__ __launch_bounds__(256) void k1b_norms() {
    int t = blockIdx.x * 8 + (threadIdx.x >> 5);
    int lane = threadIdx.x & 31;
    #pragma unroll
    for (int w2 = 0; w2 < 2; w2++) {
        const __nv_bfloat16* bh = (w2 ? g_kbh : g_qbh) + (size_t)t*DKK;
        const __nv_bfloat16* bm = (w2 ? g_kbm : g_qbm) + (size_t)t*DKK;
        uint2 hw = ((const uint2*)bh)[lane];
        uint2 mw = ((const uint2*)bm)[lane];
        __nv_bfloat162 h01 = *(__nv_bfloat162*)&hw.x, h23 = *(__nv_bfloat162*)&hw.y;
        __nv_bfloat162 m01 = *(__nv_bfloat162*)&mw.x, m23 = *(__nv_bfloat162*)&mw.y;
        float a0 = __bfloat162float(h01.x) + __bfloat162float(m01.x);
        float a1 = __bfloat162float(h01.y) + __bfloat162float(m01.y);
        float a2 = __bfloat162float(h23.x) + __bfloat162float(m23.x);
        float a3 = __bfloat162float(h23.y) + __bfloat162float(m23.y);
        float s = a0*a0 + a1*a1 + a2*a2 + a3*a3;
        #pragma unroll
        for (int o = 16; o; o >>= 1) s += __shfl_xor_sync(0xffffffffu, s, o);
        if (lane == 0) (w2 ? g_kn : g_qn)[t] = s;
    }
}

// ---------------- K2: feature projection, bf16x3, m-half per blockIdx.z -------
__global__ __launch_bounds__(256,2) void k2_mma() {
    extern __shared__ char smarr[];
    uint32_t sb = smem_u32(smarr);
    const int tid = threadIdx.x, lane = tid & 31, wid = tid >> 5;
    const int gid = lane >> 2, tig = lane & 3;
    const int wm = (wid >> 2)*64, wn = (wid & 3)*32;
    const int row0 = blockIdx.x * 128;
    const bool isK = blockIdx.y != 0;
    const int mh = blockIdx.z;                         // m half: 0 or 1
    const __nv_bfloat16* Ah = (isK ? g_kbh : g_qbh) + (size_t)row0*DKK;
    const __nv_bfloat16* Am = (isK ? g_kbm : g_qbm) + (size_t)row0*DKK;
    const __nv_bfloat16* Obh = g_ombh + (size_t)mh*128*DKK;
    const __nv_bfloat16* Obm = g_ombm + (size_t)mh*128*DKK;
    const float* nrm  = isK ? g_kn : g_qn;
    float* out        = isK ? g_pk : g_pq;
    float acc[4][4][4] = {};
    __shared__ float wmax[8];

    // stage: Ah@0, Am@1, Bh@2, Bm@3 (x BT_B)
    {
        ldB2(sb,          Ah, DKK, tid);
        ldB2(sb +   BT_B, Am, DKK, tid);
        ldB2(sb + 2*BT_B, Obh, DKK, tid);
        ldB2(sb + 3*BT_B, Obm, DKK, tid);
        CP_COMMIT();
    }
    for (int c = 0; c < 4; c++) {
        if (c+1 < 4) {
            uint32_t st = sb + ((c+1)&1)*K2_STG;
            const int o = (c+1)*32;
            ldB2(st,          Ah + o, DKK, tid);
            ldB2(st +   BT_B, Am + o, DKK, tid);
            ldB2(st + 2*BT_B, Obh + o, DKK, tid);
            ldB2(st + 3*BT_B, Obm + o, DKK, tid);
            CP_COMMIT();
            CP_WAIT1();
        } else {
            CP_WAIT0();
        }
        __syncthreads();
        const char* S = smarr + (c&1)*K2_STG;
        const __nv_bfloat16* SAh = (const __nv_bfloat16*)S;
        const __nv_bfloat16* SAm = (const __nv_bfloat16*)(S + BT_B);
        const __nv_bfloat16* SBh = (const __nv_bfloat16*)(S + 2*BT_B);
        const __nv_bfloat16* SBm = (const __nv_bfloat16*)(S + 3*BT_B);
        coreRB(SAh, SBh, acc, wm, wn, gid, tig);
        coreRB(SAh, SBm, acc, wm, wn, gid, tig);
        coreRB(SAm, SBh, acc, wm, wn, gid, tig);
        __syncthreads();
    }
    float lmax = __int_as_float(0xff800000);
    #pragma unroll
    for (int im = 0; im < 4; im++) {
        #pragma unroll
        for (int jn = 0; jn < 4; jn++) {
            int row = row0 + wm + im*16 + gid;
            int col = mh*128 + wn + jn*8 + tig*2;
            float hn0 = 0.5f * nrm[row], hn1 = 0.5f * nrm[row+8];
            float2 v;
            v.x = acc[im][jn][0] - hn0; v.y = acc[im][jn][1] - hn0;
            *(float2*)(out + (size_t)row*MM + col) = v;
            if (isK) lmax = fmaxf(lmax, fmaxf(v.x, v.y));
            v.x = acc[im][jn][2] - hn1; v.y = acc[im][jn][3] - hn1;
            *(float2*)(out + (size_t)(row+8)*MM + col) = v;
            if (isK) lmax = fmaxf(lmax, fmaxf(v.x, v.y));
        }
    }
    if (isK) {   // fused global pk max
        #pragma unroll
        for (int o = 16; o; o >>= 1) lmax = fmaxf(lmax, __shfl_xor_sync(0xffffffffu, lmax, o));
        if (lane == 0) wmax[wid] = lmax;
        __syncthreads();
        if (tid == 0) {
            float bm = wmax[0];
            #pragma unroll
            for (int w = 1; w < 8; w++) bm = fmaxf(bm, wmax[w]);
            atomicMaxFloat(&g_gkmax, bm);
        }
    }
}

// ---------------- K3a: phi_q = rnd(exp(pq - rowmax)/16) -----------------------
__global__ __launch_bounds__(256) void k3a() {
    int t = blockIdx.x * 8 + (threadIdx.x >> 5);
    int lane = threadIdx.x & 31;
    float* pq = g_pq + (size_t)t*MM;
    float4 v0 = *(float4*)(pq + lane*4);
    float4 v1 = *(float4*)(pq + 128 + lane*4);
    float mx = fmaxf(fmaxf(fmaxf(v0.x, v0.y), fmaxf(v0.z, v0.w)),
                     fmaxf(fmaxf(v1.x, v1.y), fmaxf(v1.z, v1.w)));
    #pragma unroll
    for (int o = 16; o; o >>= 1) mx = fmaxf(mx, __shfl_xor_sync(0xffffffffu, mx, o));
    float4 e0, e1;
    e0.x = rndtf(expf(v0.x - mx)*0.0625f); e0.y = rndtf(expf(v0.y - mx)*0.0625f);
    e0.z = rndtf(expf(v0.z - mx)*0.0625f); e0.w = rndtf(expf(v0.w - mx)*0.0625f);
    e1.x = rndtf(expf(v1.x - mx)*0.0625f); e1.y = rndtf(expf(v1.y - mx)*0.0625f);
    e1.z = rndtf(expf(v1.z - mx)*0.0625f); e1.w = rndtf(expf(v1.w - mx)*0.0625f);
    *(float4*)(pq + lane*4) = e0;
    *(float4*)(pq + 128 + lane*4) = e1;
}

// ---------------- K3b: phi_k = rnd(exp(pk - gmax)/16) -------------------------
__global__ __launch_bounds__(256) void k3b() {
    float gm = g_gkmax;
    size_t n4 = (size_t)TT*MM/4;
    size_t stride = (size_t)gridDim.x * blockDim.x;
    for (size_t i = (size_t)blockIdx.x*blockDim.x + threadIdx.x; i < n4; i += stride) {
        float4 v = ((float4*)g_pk)[i];
        v.x = rndtf(expf(v.x - gm)*0.0625f); v.y = rndtf(expf(v.y - gm)*0.0625f);
        v.z = rndtf(expf(v.z - gm)*0.0625f); v.w = rndtf(expf(v.w - gm)*0.0625f);
        ((float4*)g_pk)[i] = v;
    }
}

// ---------------- K4: kvT[b][d][m] += sum_s phi_k[s][m] v[s][d] ---------------
__global__ __launch_bounds__(256,2) void k4_mma() {
    extern __shared__ char smarr[];
    uint32_t sb = smem_u32(smarr);
    const int tid = threadIdx.x, lane = tid & 31, wid = tid >> 5;
    const int gid = lane >> 2, tig = lane & 3;
    const int wm = (wid >> 2)*64, wn = (wid & 3)*32;
    const int b = blockIdx.x, m0 = blockIdx.y * 128, sp = blockIdx.z;
    const float* Asrc = g_pk + ((size_t)b*SS + sp*512)*MM + m0;
    const float* Bsrc = g_vr + ((size_t)b*SS + sp*512)*DVV;
    float acc[4][4][4] = {};

    { ldT4(sb, Asrc, MM, tid); ldT4(sb + TILE_B, Bsrc, DVV, tid); CP_COMMIT(); }
    for (int c = 0; c < 16; c++) {
        if (c+1 < 16) {
            uint32_t st = sb + ((c+1)&1)*STG2_B;
            ldT4(st, Asrc + (size_t)(c+1)*32*MM, MM, tid);
            ldT4(st + TILE_B, Bsrc + (size_t)(c+1)*32*DVV, DVV, tid);
            CP_COMMIT();
            CP_WAIT1();
        } else {
            CP_WAIT0();
        }
        __syncthreads();
        const float* S = (const float*)(smarr + (c&1)*STG2_B);
        coreT(S, S + TILE_F, acc, wm, wn, gid, tig);
        __syncthreads();
    }
    float* kvb = g_kvT + (size_t)b*DVV*MM;
    #pragma unroll
    for (int im = 0; im < 4; im++) {
        #pragma unroll
        for (int jn = 0; jn < 4; jn++) {
            int m = m0 + wm + im*16 + gid;
            int d = wn + jn*8 + tig*2;
            atomicAdd(&kvb[(size_t)d*MM + m],       acc[im][jn][0]);
            atomicAdd(&kvb[(size_t)(d+1)*MM + m],   acc[im][jn][1]);
            atomicAdd(&kvb[(size_t)d*MM + m+8],     acc[im][jn][2]);
            atomicAdd(&kvb[(size_t)(d+1)*MM + m+8], acc[im][jn][3]);
        }
    }
}

// ---------------- K4c: round kvT in place -------------------------------------
__global__ __launch_bounds__(256) void k4c_round() {
    int i = blockIdx.x * 256 + threadIdx.x;
    int n = BB*DVV*MM;
    for (; i < n; i += gridDim.x * 256) g_kvT[i] = rndtf(g_kvT[i]);
}

// ---------------- K4b: ksum[b,m] = sum_s phi_k --------------------------------
__global__ __launch_bounds__(256) void k4b_ksum() {
    int b = blockIdx.x, chunk = blockIdx.y, m = threadIdx.x;
    const float* Pk = g_pk + ((size_t)b*SS + chunk*128)*MM + m;
    float s = 0.0f;
    #pragma unroll 8
    for (int i = 0; i < 128; i++) s += Pk[(size_t)i*MM];
    atomicAdd(&g_ksum[b*MM + m], s);
}

// ---------------- K5a: den[t] = dot(phi_q[t], ksum[b]) + eps ------------------
__global__ __launch_bounds__(256) void k5a_den() {
    int t = blockIdx.x * 8 + (threadIdx.x >> 5);
    int lane = threadIdx.x & 31;
    int b = t >> 12;
    const float* pq = g_pq + (size_t)t*MM;
    const float* ks = g_ksum + b*MM;
    float4 p0 = *(const float4*)(pq + lane*4);
    float4 p1 = *(const float4*)(pq + 128 + lane*4);
    float4 k0 = *(const float4*)(ks + lane*4);
    float4 k1 = *(const float4*)(ks + 128 + lane*4);
    float s = p0.x*k0.x + p0.y*k0.y + p0.z*k0.z + p0.w*k0.w
            + p1.x*k1.x + p1.y*k1.y + p1.z*k1.z + p1.w*k1.w;
    #pragma unroll
    for (int o = 16; o; o >>= 1) s += __shfl_xor_sync(0xffffffffu, s, o);
    if (lane == 0) g_den[t] = s + EPSV;
}

// ---------------- K5: out = (phi_q @ kv) / den --------------------------------
__global__ __launch_bounds__(256,2) void k5_mma(float* __restrict__ out) {
    extern __shared__ char smarr[];
    uint32_t sb = smem_u32(smarr);
    const int tid = threadIdx.x, lane = tid & 31, wid = tid >> 5;
    const int gid = lane >> 2, tig = lane & 3;
    const int wm = (wid >> 2)*64, wn = (wid & 3)*32;
    const int row0 = blockIdx.x * 128;
    const int b = blockIdx.x >> 5;
    const float* Asrc = g_pq + (size_t)row0*MM;
    const float* Bsrc = g_kvT + (size_t)b*DVV*MM;
    float acc[4][4][4] = {};

    { ldR4(sb, Asrc, MM, tid); ldR4(sb + TILE_B, Bsrc, MM, tid); CP_COMMIT(); }
    for (int c = 0; c < 8; c++) {
        if (c+1 < 8) {
            uint32_t st = sb + ((c+1)&1)*STG2_B;
            ldR4(st, Asrc + (c+1)*32, MM, tid);
            ldR4(st + TILE_B, Bsrc + (c+1)*32, MM, tid);
            CP_COMMIT();
            CP_WAIT1();
        } else {
            CP_WAIT0();
        }
        __syncthreads();
        const float* S = (const float*)(smarr + (c&1)*STG2_B);
        coreR(S, S + TILE_F, acc, wm, wn, gid, tig);
        __syncthreads();
    }
    #pragma unroll
    for (int im = 0; im < 4; im++) {
        #pragma unroll
        for (int jn = 0; jn < 4; jn++) {
            int row = row0 + wm + im*16 + gid;
            int col = wn + jn*8 + tig*2;
            float inv0 = 1.0f / g_den[row], inv1 = 1.0f / g_den[row+8];
            float2 v;
            v.x = acc[im][jn][0]*inv0; v.y = acc[im][jn][1]*inv0;
            *(float2*)(out + (size_t)row*DVV + col) = v;
            v.x = acc[im][jn][2]*inv1; v.y = acc[im][jn][3]*inv1;
            *(float2*)(out + (size_t)(row+8)*DVV + col) = v;
        }
    }
}

// ---------------- launch ------------------------------------------------------
extern "C" void kernel_launch(void* const* d_in, const int* in_sizes, int n_in,
                              void* d_out, int out_size) {
    const float* x     = (const float*)d_in[0];
    const float* Wq    = (const float*)d_in[1];
    const float* bq    = (const float*)d_in[2];
    const float* Wk    = (const float*)d_in[3];
    const float* bk    = (const float*)d_in[4];
    const float* Wv    = (const float*)d_in[5];
    const float* bv    = (const float*)d_in[6];
    const float* omega = (const float*)d_in[7];
    float* out = (float*)d_out;

    cudaFuncSetAttribute(k1_qk,  cudaFuncAttributeMaxDynamicSharedMemorySize, SMEM_QK);
    cudaFuncSetAttribute(k1_v,   cudaFuncAttributeMaxDynamicSharedMemorySize, SMEM_V);
    cudaFuncSetAttribute(k2_mma, cudaFuncAttributeMaxDynamicSharedMemorySize, SMEM_K2);
    cudaFuncSetAttribute(k4_mma, cudaFuncAttributeMaxDynamicSharedMemorySize, SMEM2);
    cudaFuncSetAttribute(k5_mma, cudaFuncAttributeMaxDynamicSharedMemorySize, SMEM2);

    k_prep_w<<<1536, 256>>>(Wq, Wk, Wv);
    k_prep_om<<<128, 256>>>(omega);
    k0_init<<<64, 256>>>();
    k1_qk<<<dim3(256, 2), 256, SMEM_QK>>>(x, bq, bk);
    k1_v<<<256, 256, SMEM_V>>>(x, bv);
    k1b_norms<<<TT/8, 256>>>();
    k2_mma<<<dim3(256, 2, 2), 256, SMEM_K2>>>();
    k3a<<<TT/8, 256>>>();
    k3b<<<2048, 256>>>();
    k4_mma<<<dim3(8, 2, 8), 256, SMEM2>>>();
    k4c_round<<<256, 256>>>();
    k4b_ksum<<<dim3(8, 32), 256>>>();
    k5a_den<<<TT/8, 256>>>();
    k5_mma<<<256, 256, SMEM2>>>(out);
}

// round 10
// speedup vs baseline: 2.7020x; 1.0474x over previous
#include <cuda_runtime.h>
#include <cuda_bf16.h>
#include <math.h>
#include <stdint.h>

#define BB 8
#define SS 4096
#define TT (BB*SS)          // 32768 tokens
#define DD 1024
#define DKK 128
#define DVV 128
#define MM 256
#define EPSV 1e-6f

#define LDR 36              // fp32 row-major smem leading dim (floats)
#define LDT 136             // fp32 k-major smem leading dim (floats)
#define LDB 40              // bf16 row-major smem leading dim (elements)
#define TILE_B 18432        // fp32 128x32 tile w/ pad, bytes
#define TILE_F 4608
#define BT_B 10240          // bf16 128x(32 pad 40) tile, bytes

#define QK_STG (TILE_B + 4*BT_B)          // Xraw + Bqh,Bqm,Bkh,Bkm = 59392
#define SMEM_QK (2*QK_STG + 2*BT_B)       // + Ah, Am = 139264 (1 CTA/SM)
#define V_STG (2*TILE_B)
#define SMEM_V (2*V_STG + TILE_B)         // 92160 (2 CTA/SM)
#define K2_STG (4*BT_B)                   // Ah, Am, Bh, Bm = 40960
#define SMEM_K2 (2*K2_STG)                // 81920 (2 CTA/SM)
#define STG2_B (2*TILE_B)
#define SMEM2 (2*STG2_B)                  // 73728 (k4, k5)

// ---------------- scratch (device globals; no allocation allowed) -------------
__device__ __align__(128) __nv_bfloat16 g_Wbh[256*DD];   // Wq|Wk transposed [n][k], hi
__device__ __align__(128) __nv_bfloat16 g_Wbm[256*DD];   // mid
__device__ float g_Wvf[128*DD];                          // Wv transposed, tf32-rounded
__device__ __align__(128) __nv_bfloat16 g_ombh[MM*DKK];
__device__ __align__(128) __nv_bfloat16 g_ombm[MM*DKK];
__device__ __align__(128) __nv_bfloat16 g_qbh[(size_t)TT*DKK];
__device__ __align__(128) __nv_bfloat16 g_qbm[(size_t)TT*DKK];
__device__ __align__(128) __nv_bfloat16 g_kbh[(size_t)TT*DKK];
__device__ __align__(128) __nv_bfloat16 g_kbm[(size_t)TT*DKK];
__device__ float g_vr[(size_t)TT*DVV];      // v, tf32-rounded
__device__ float g_pq[(size_t)TT*MM];       // logits, then phi_q (tf32-rounded)
__device__ float g_pk[(size_t)TT*MM];
__device__ float g_qn[TT];
__device__ float g_kn[TT];
__device__ float g_den[TT];
__device__ float g_kvT[BB*DVV*MM];          // kv transposed [b][d][m]
__device__ float g_ksum[BB*MM];
__device__ float g_gkmax;

// ---------------- helpers -----------------------------------------------------
__device__ __forceinline__ uint32_t smem_u32(const void* p) {
    uint32_t a;
    asm("{ .reg .u64 t; cvta.to.shared.u64 t, %1; cvt.u32.u64 %0, t; }" : "=r"(a) : "l"(p));
    return a;
}
__device__ __forceinline__ float rndtf(float x) {
    uint32_t r; asm("cvt.rna.tf32.f32 %0, %1;" : "=r"(r) : "f"(x));
    return __uint_as_float(r);
}
__device__ __forceinline__ void atomicMaxFloat(float* addr, float v) {
    if (v >= 0.0f) atomicMax((int*)addr, __float_as_int(v));
    else           atomicMin((unsigned int*)addr, __float_as_uint(v));
}
__device__ __forceinline__ void cpa16(uint32_t d, const void* s) {
    asm volatile("cp.async.cg.shared.global [%0], [%1], 16;" :: "r"(d), "l"(s));
}
#define CP_COMMIT() asm volatile("cp.async.commit_group;" ::: "memory")
#define CP_WAIT0()  asm volatile("cp.async.wait_group 0;" ::: "memory")
#define CP_WAIT1()  asm volatile("cp.async.wait_group 1;" ::: "memory")

#define MMA8(d, a, b) \
    asm volatile("mma.sync.aligned.m16n8k8.row.col.f32.tf32.tf32.f32 " \
        "{%0,%1,%2,%3}, {%4,%5,%6,%7}, {%8,%9}, {%0,%1,%2,%3};" \
        : "+f"((d)[0]), "+f"((d)[1]), "+f"((d)[2]), "+f"((d)[3]) \
        : "r"((a)[0]), "r"((a)[1]), "r"((a)[2]), "r"((a)[3]), \
          "r"((b)[0]), "r"((b)[1]))

#define MMA16(d, a, b) \
    asm volatile("mma.sync.aligned.m16n8k16.row.col.f32.bf16.bf16.f32 " \
        "{%0,%1,%2,%3}, {%4,%5,%6,%7}, {%8,%9}, {%0,%1,%2,%3};" \
        : "+f"((d)[0]), "+f"((d)[1]), "+f"((d)[2]), "+f"((d)[3]) \
        : "r"((a)[0]), "r"((a)[1]), "r"((a)[2]), "r"((a)[3]), \
          "r"((b)[0]), "r"((b)[1]))

#define LDSM4(r0, r1, r2, r3, addr) \
    asm volatile("ldmatrix.sync.aligned.m8n8.x4.shared.b16 {%0,%1,%2,%3}, [%4];" \
        : "=r"(r0), "=r"(r1), "=r"(r2), "=r"(r3) : "r"(addr))

// fp32 loaders
__device__ __forceinline__ void ldR4(uint32_t sb, const float* src, int ldg, int tid) {
    #pragma unroll
    for (int t = 0; t < 4; t++) {
        int idx = tid + t*256, r = idx >> 3, c = idx & 7;
        cpa16(sb + (uint32_t)(r*LDR + c*4)*4u, src + (size_t)r*ldg + c*4);
    }
}
__device__ __forceinline__ void ldT4(uint32_t sb, const float* src, int ldg, int tid) {
    #pragma unroll
    for (int t = 0; t < 4; t++) {
        int idx = tid + t*256, r = idx >> 5, c = idx & 31;
        cpa16(sb + (uint32_t)(r*LDT + c*4)*4u, src + (size_t)r*ldg + c*4);
    }
}
// bf16 tile loader: 128 rows x 32 elements (64B/row), into [row][LDB] bf16
__device__ __forceinline__ void ldB2(uint32_t sb, const __nv_bfloat16* src, int ldg, int tid) {
    #pragma unroll
    for (int t = 0; t < 2; t++) {
        int idx = tid + t*256, r = idx >> 2, c = idx & 3;
        cpa16(sb + (uint32_t)(r*(LDB*2) + c*16), src + (size_t)r*ldg + c*8);
    }
}

// 64x32 warp tile, fp32 tf32 mma, smem layout R ([row][k], ld 36)
__device__ __forceinline__ void coreR(const float* As, const float* Bs,
                                      float acc[4][4][4], int wm, int wn, int gid, int tig) {
    #pragma unroll
    for (int k8 = 0; k8 < 32; k8 += 8) {
        uint32_t a[4][4], b[4][2];
        #pragma unroll
        for (int im = 0; im < 4; im++) {
            int rb = wm + im*16;
            a[im][0] = __float_as_uint(As[(rb+gid  )*LDR + k8+tig  ]);
            a[im][1] = __float_as_uint(As[(rb+gid+8)*LDR + k8+tig  ]);
            a[im][2] = __float_as_uint(As[(rb+gid  )*LDR + k8+tig+4]);
            a[im][3] = __float_as_uint(As[(rb+gid+8)*LDR + k8+tig+4]);
        }
        #pragma unroll
        for (int jn = 0; jn < 4; jn++) {
            int nb = wn + jn*8;
            b[jn][0] = __float_as_uint(Bs[(nb+gid)*LDR + k8+tig  ]);
            b[jn][1] = __float_as_uint(Bs[(nb+gid)*LDR + k8+tig+4]);
        }
        #pragma unroll
        for (int im = 0; im < 4; im++)
            #pragma unroll
            for (int jn = 0; jn < 4; jn++)
                MMA8(acc[im][jn], a[im], b[jn]);
    }
}
// fp32 tf32 mma, smem layout T ([k][row], ld 136)
__device__ __forceinline__ void coreT(const float* As, const float* Bs,
                                      float acc[4][4][4], int wm, int wn, int gid, int tig) {
    #pragma unroll
    for (int k8 = 0; k8 < 32; k8 += 8) {
        uint32_t a[4][4], b[4][2];
        #pragma unroll
        for (int im = 0; im < 4; im++) {
            int rb = wm + im*16;
            a[im][0] = __float_as_uint(As[(k8+tig  )*LDT + rb+gid  ]);
            a[im][1] = __float_as_uint(As[(k8+tig  )*LDT + rb+gid+8]);
            a[im][2] = __float_as_uint(As[(k8+tig+4)*LDT + rb+gid  ]);
            a[im][3] = __float_as_uint(As[(k8+tig+4)*LDT + rb+gid+8]);
        }
        #pragma unroll
        for (int jn = 0; jn < 4; jn++) {
            int nb = wn + jn*8;
            b[jn][0] = __float_as_uint(Bs[(k8+tig  )*LDT + nb+gid]);
            b[jn][1] = __float_as_uint(Bs[(k8+tig+4)*LDT + nb+gid]);
        }
        #pragma unroll
        for (int im = 0; im < 4; im++)
            #pragma unroll
            for (int jn = 0; jn < 4; jn++)
                MMA8(acc[im][jn], a[im], b[jn]);
    }
}
// 64x32 warp tile, bf16 m16n8k16 mma via ldmatrix; As/Bs = smem BYTE addresses
__device__ __forceinline__ void coreRB(uint32_t As, uint32_t Bs,
                                       float acc[4][4][4], int wm, int wn, int lane) {
    const int l15 = lane & 15;
    const int ahi = (lane >> 4) & 1;          // A: col half
    const int l7  = lane & 7;
    const int bk  = (lane >> 3) & 1;          // B: k half
    const int bn  = (lane >> 4) & 1;          // B: jn within pair
    #pragma unroll
    for (int k16 = 0; k16 < 32; k16 += 16) {
        uint32_t a[4][4], b[4][2];
        #pragma unroll
        for (int im = 0; im < 4; im++) {
            uint32_t addr = As + (uint32_t)((wm + im*16 + l15)*LDB + k16 + ahi*8)*2u;
            LDSM4(a[im][0], a[im][1], a[im][2], a[im][3], addr);
        }
        #pragma unroll
        for (int jp = 0; jp < 2; jp++) {
            uint32_t addr = Bs + (uint32_t)((wn + jp*16 + bn*8 + l7)*LDB + k16 + bk*8)*2u;
            uint32_t r0, r1, r2, r3;
            LDSM4(r0, r1, r2, r3, addr);
            b[jp*2  ][0] = r0; b[jp*2  ][1] = r1;
            b[jp*2+1][0] = r2; b[jp*2+1][1] = r3;
        }
        #pragma unroll
        for (int im = 0; im < 4; im++)
            #pragma unroll
            for (int jn = 0; jn < 4; jn++)
                MMA16(acc[im][jn], a[im], b[jn]);
    }
}

// ---------------- prep kernels ------------------------------------------------
__global__ __launch_bounds__(256) void k_prep_w(
    const float* __restrict__ Wq, const float* __restrict__ Wk, const float* __restrict__ Wv) {
    int idx = blockIdx.x * 256 + threadIdx.x;          // 0..393215
    int row = idx >> 10, k = idx & 1023;
    if (row < 256) {
        const float* W = (row < 128) ? Wq : Wk;
        int n = row & 127;
        float v = W[(size_t)k * DKK + n];
        __nv_bfloat16 h = __float2bfloat16_rn(v);
        g_Wbh[idx] = h;
        g_Wbm[idx] = __float2bfloat16_rn(v - __bfloat162float(h));
    } else {
        int n = row & 127;
        g_Wvf[(size_t)(row - 256)*DD + k] = rndtf(Wv[(size_t)k * DKK + n]);
    }
}
__global__ __launch_bounds__(256) void k_prep_om(const float* __restrict__ om) {
    int idx = blockIdx.x * 256 + threadIdx.x;          // 0..32767
    float v = om[idx];
    __nv_bfloat16 h = __float2bfloat16_rn(v);
    g_ombh[idx] = h;
    g_ombm[idx] = __float2bfloat16_rn(v - __bfloat162float(h));
}
__global__ void k0_init() {
    int tid = blockIdx.x * blockDim.x + threadIdx.x;
    int nt  = gridDim.x * blockDim.x;
    if (tid == 0) g_gkmax = __int_as_float(0xff800000);
    for (int i = tid; i < BB*DVV*MM; i += nt) g_kvT[i] = 0.0f;
    for (int i = tid; i < BB*MM;     i += nt) g_ksum[i] = 0.0f;
}

// split raw fp32 tile (layout R) -> bf16 hi/mid tiles (layout [r][LDB])
__device__ __forceinline__ void split_bf(const float* Xr, __nv_bfloat16* Hp,
                                         __nv_bfloat16* Mp, int tid) {
    int r = tid >> 1, c0 = (tid & 1) * 16;
    #pragma unroll
    for (int j = 0; j < 4; j++) {
        float4 v = *(const float4*)&Xr[r*LDR + c0 + j*4];
        __nv_bfloat16 hx = __float2bfloat16_rn(v.x);
        __nv_bfloat16 hy = __float2bfloat16_rn(v.y);
        __nv_bfloat16 hz = __float2bfloat16_rn(v.z);
        __nv_bfloat16 hw = __float2bfloat16_rn(v.w);
        *(__nv_bfloat162*)&Hp[r*LDB + c0 + j*4]     = __halves2bfloat162(hx, hy);
        *(__nv_bfloat162*)&Hp[r*LDB + c0 + j*4 + 2] = __halves2bfloat162(hz, hw);
        __nv_bfloat16 mx = __float2bfloat16_rn(v.x - __bfloat162float(hx));
        __nv_bfloat16 my = __float2bfloat16_rn(v.y - __bfloat162float(hy));
        __nv_bfloat16 mz = __float2bfloat16_rn(v.z - __bfloat162float(hz));
        __nv_bfloat16 mw = __float2bfloat16_rn(v.w - __bfloat162float(hw));
        *(__nv_bfloat162*)&Mp[r*LDB + c0 + j*4]     = __halves2bfloat162(mx, my);
        *(__nv_bfloat162*)&Mp[r*LDB + c0 + j*4 + 2] = __halves2bfloat162(mz, mw);
    }
}
// split hi-only to tf32 fp32 tile (for v path)
__device__ __forceinline__ void split_tf(const float* Xr, float* Ahp, int tid) {
    int r = tid >> 1, c0 = (tid & 1) * 16;
    #pragma unroll
    for (int j = 0; j < 4; j++) {
        float4 v = *(const float4*)&Xr[r*LDR + c0 + j*4];
        float4 h;
        h.x = rndtf(v.x); h.y = rndtf(v.y); h.z = rndtf(v.z); h.w = rndtf(v.w);
        *(float4*)&Ahp[r*LDR + c0 + j*4] = h;
    }
}

// ---------------- K1a: fused q+k GEMM, bf16 2-split 3-product, ldmatrix -------
__global__ __launch_bounds__(256,1) void k1_qk(
    const float* __restrict__ x, const float* __restrict__ bq, const float* __restrict__ bk) {
    extern __shared__ char smarr[];
    uint32_t sb = smem_u32(smarr);
    const int tid = threadIdx.x, lane = tid & 31, wid = tid >> 5;
    const int gid = lane >> 2, tig = lane & 3;
    const int wm = (wid >> 2)*64, wn = (wid & 3)*32;
    const int row0 = blockIdx.x * 128;
    const float* X = x + (size_t)row0*DD;
    const __nv_bfloat16* Wqh = g_Wbh;
    const __nv_bfloat16* Wqm = g_Wbm;
    const __nv_bfloat16* Wkh = g_Wbh + (size_t)128*DD;
    const __nv_bfloat16* Wkm = g_Wbm + (size_t)128*DD;
    const uint32_t Ahp_a = sb + 2*QK_STG;
    const uint32_t Amp_a = Ahp_a + BT_B;
    __nv_bfloat16* Ahp = (__nv_bfloat16*)(smarr + 2*QK_STG);
    __nv_bfloat16* Amp = Ahp + BT_B/2;
    float accq[4][4][4] = {}, acck[4][4][4] = {};

    {   // prologue
        ldR4(sb, X, DD, tid);
        ldB2(sb + TILE_B,          Wqh, DD, tid);
        ldB2(sb + TILE_B + BT_B,   Wqm, DD, tid);
        ldB2(sb + TILE_B + 2*BT_B, Wkh, DD, tid);
        ldB2(sb + TILE_B + 3*BT_B, Wkm, DD, tid);
        CP_COMMIT();
    }
    for (int c = 0; c < 32; c++) {
        CP_WAIT0();
        __syncthreads();                     // data(c) ready; compute(c-1) done
        if (c+1 < 32) {
            uint32_t st = sb + ((c+1)&1)*QK_STG;
            const int o = (c+1)*32;
            ldR4(st, X + o, DD, tid);
            ldB2(st + TILE_B,          Wqh + o, DD, tid);
            ldB2(st + TILE_B + BT_B,   Wqm + o, DD, tid);
            ldB2(st + TILE_B + 2*BT_B, Wkh + o, DD, tid);
            ldB2(st + TILE_B + 3*BT_B, Wkm + o, DD, tid);
            CP_COMMIT();
        }
        const uint32_t S = sb + (c&1)*QK_STG;
        split_bf((const float*)(smarr + (c&1)*QK_STG), Ahp, Amp, tid);
        __syncthreads();                     // Ah/Am ready
        coreRB(Ahp_a, S + TILE_B,          accq, wm, wn, lane);   // Ah*Bqh
        coreRB(Ahp_a, S + TILE_B + BT_B,   accq, wm, wn, lane);   // Ah*Bqm
        coreRB(Amp_a, S + TILE_B,          accq, wm, wn, lane);   // Am*Bqh
        coreRB(Ahp_a, S + TILE_B + 2*BT_B, acck, wm, wn, lane);
        coreRB(Ahp_a, S + TILE_B + 3*BT_B, acck, wm, wn, lane);
        coreRB(Amp_a, S + TILE_B + 2*BT_B, acck, wm, wn, lane);
    }
    const float QKS = 0.29730177875068026f;   // 128^-0.25
    #pragma unroll
    for (int w2 = 0; w2 < 2; w2++) {
        float (*acc)[4][4] = w2 ? acck : accq;
        const float* bias  = w2 ? bk : bq;
        __nv_bfloat16* oh = w2 ? g_kbh : g_qbh;
        __nv_bfloat16* om = w2 ? g_kbm : g_qbm;
        #pragma unroll
        for (int im = 0; im < 4; im++) {
            #pragma unroll
            for (int jn = 0; jn < 4; jn++) {
                int row = row0 + wm + im*16 + gid;
                int col = wn + jn*8 + tig*2;
                float b0 = bias[col], b1 = bias[col+1];
                #pragma unroll
                for (int half = 0; half < 2; half++) {
                    float f0 = (acc[im][jn][half*2+0] + b0)*QKS;
                    float f1 = (acc[im][jn][half*2+1] + b1)*QKS;
                    size_t off = (size_t)(row + half*8)*128 + col;
                    __nv_bfloat16 h0 = __float2bfloat16_rn(f0);
                    __nv_bfloat16 h1 = __float2bfloat16_rn(f1);
                    *(__nv_bfloat162*)(oh + off) = __halves2bfloat162(h0, h1);
                    __nv_bfloat16 m0 = __float2bfloat16_rn(f0 - __bfloat162float(h0));
                    __nv_bfloat16 m1 = __float2bfloat16_rn(f1 - __bfloat162float(h1));
                    *(__nv_bfloat162*)(om + off) = __halves2bfloat162(m0, m1);
                }
            }
        }
    }
}

// ---------------- K1c: v GEMM, single tf32 ------------------------------------
__global__ __launch_bounds__(256,2) void k1_v(
    const float* __restrict__ x, const float* __restrict__ bv) {
    extern __shared__ char smarr[];
    uint32_t sb = smem_u32(smarr);
    const int tid = threadIdx.x, lane = tid & 31, wid = tid >> 5;
    const int gid = lane >> 2, tig = lane & 3;
    const int wm = (wid >> 2)*64, wn = (wid & 3)*32;
    const int row0 = blockIdx.x * 128;
    const float* X = x + (size_t)row0*DD;
    float* Ahp = (float*)(smarr + 2*V_STG);
    float acc[4][4][4] = {};

    { ldR4(sb, X, DD, tid); ldR4(sb + TILE_B, g_Wvf, DD, tid); CP_COMMIT(); }
    for (int c = 0; c < 32; c++) {
        CP_WAIT0();
        __syncthreads();
        if (c+1 < 32) {
            uint32_t st = sb + ((c+1)&1)*V_STG;
            ldR4(st, X + (c+1)*32, DD, tid);
            ldR4(st + TILE_B, g_Wvf + (c+1)*32, DD, tid);
            CP_COMMIT();
        }
        const float* S = (const float*)(smarr + (c&1)*V_STG);
        split_tf(S, Ahp, tid);
        __syncthreads();
        coreR(Ahp, S + TILE_F, acc, wm, wn, gid, tig);
    }
    #pragma unroll
    for (int im = 0; im < 4; im++) {
        #pragma unroll
        for (int jn = 0; jn < 4; jn++) {
            int row = row0 + wm + im*16 + gid;
            int col = wn + jn*8 + tig*2;
            float b0 = bv[col], b1 = bv[col+1];
            float2 v;
            v.x = rndtf(acc[im][jn][0] + b0); v.y = rndtf(acc[im][jn][1] + b1);
            *(float2*)(g_vr + (size_t)row*128 + col) = v;
            v.x = rndtf(acc[im][jn][2] + b0); v.y = rndtf(acc[im][jn][3] + b1);
            *(float2*)(g_vr + (size_t)(row+8)*128 + col) = v;
        }
    }
}

// ---------------- K1b: row norms of q, k (h+m) --------------------------------
__global__ __launch_bounds__(256) void k1b_norms() {
    int t = blockIdx.x * 8 + (threadIdx.x >> 5);
    int lane = threadIdx.x & 31;
    #pragma unroll
    for (int w2 = 0; w2 < 2; w2++) {
        const __nv_bfloat16* bh = (w2 ? g_kbh : g_qbh) + (size_t)t*DKK;
        const __nv_bfloat16* bm = (w2 ? g_kbm : g_qbm) + (size_t)t*DKK;
        uint2 hw = ((const uint2*)bh)[lane];
        uint2 mw = ((const uint2*)bm)[lane];
        __nv_bfloat162 h01 = *(__nv_bfloat162*)&hw.x, h23 = *(__nv_bfloat162*)&hw.y;
        __nv_bfloat162 m01 = *(__nv_bfloat162*)&mw.x, m23 = *(__nv_bfloat162*)&mw.y;
        float a0 = __bfloat162float(h01.x) + __bfloat162float(m01.x);
        float a1 = __bfloat162float(h01.y) + __bfloat162float(m01.y);
        float a2 = __bfloat162float(h23.x) + __bfloat162float(m23.x);
        float a3 = __bfloat162float(h23.y) + __bfloat162float(m23.y);
        float s = a0*a0 + a1*a1 + a2*a2 + a3*a3;
        #pragma unroll
        for (int o = 16; o; o >>= 1) s += __shfl_xor_sync(0xffffffffu, s, o);
        if (lane == 0) (w2 ? g_kn : g_qn)[t] = s;
    }
}

// ---------------- K2: feature projection, bf16x3 + ldmatrix, m-half split -----
__global__ __launch_bounds__(256,2) void k2_mma() {
    extern __shared__ char smarr[];
    uint32_t sb = smem_u32(smarr);
    const int tid = threadIdx.x, lane = tid & 31, wid = tid >> 5;
    const int gid = lane >> 2, tig = lane & 3;
    const int wm = (wid >> 2)*64, wn = (wid & 3)*32;
    const int row0 = blockIdx.x * 128;
    const bool isK = blockIdx.y != 0;
    const int mh = blockIdx.z;                         // m half: 0 or 1
    const __nv_bfloat16* Ah = (isK ? g_kbh : g_qbh) + (size_t)row0*DKK;
    const __nv_bfloat16* Am = (isK ? g_kbm : g_qbm) + (size_t)row0*DKK;
    const __nv_bfloat16* Obh = g_ombh + (size_t)mh*128*DKK;
    const __nv_bfloat16* Obm = g_ombm + (size_t)mh*128*DKK;
    const float* nrm  = isK ? g_kn : g_qn;
    float* out        = isK ? g_pk : g_pq;
    float acc[4][4][4] = {};
    __shared__ float wmax[8];

    // stage: Ah@0, Am@1, Bh@2, Bm@3 (x BT_B)
    {
        ldB2(sb,          Ah, DKK, tid);
        ldB2(sb +   BT_B, Am, DKK, tid);
        ldB2(sb + 2*BT_B, Obh, DKK, tid);
        ldB2(sb + 3*BT_B, Obm, DKK, tid);
        CP_COMMIT();
    }
    for (int c = 0; c < 4; c++) {
        if (c+1 < 4) {
            uint32_t st = sb + ((c+1)&1)*K2_STG;
            const int o = (c+1)*32;
            ldB2(st,          Ah + o, DKK, tid);
            ldB2(st +   BT_B, Am + o, DKK, tid);
            ldB2(st + 2*BT_B, Obh + o, DKK, tid);
            ldB2(st + 3*BT_B, Obm + o, DKK, tid);
            CP_COMMIT();
            CP_WAIT1();
        } else {
            CP_WAIT0();
        }
        __syncthreads();
        const uint32_t S = sb + (c&1)*K2_STG;
        coreRB(S,        S + 2*BT_B, acc, wm, wn, lane);
        coreRB(S,        S + 3*BT_B, acc, wm, wn, lane);
        coreRB(S + BT_B, S + 2*BT_B, acc, wm, wn, lane);
        __syncthreads();
    }
    float lmax = __int_as_float(0xff800000);
    #pragma unroll
    for (int im = 0; im < 4; im++) {
        #pragma unroll
        for (int jn = 0; jn < 4; jn++) {
            int row = row0 + wm + im*16 + gid;
            int col = mh*128 + wn + jn*8 + tig*2;
            float hn0 = 0.5f * nrm[row], hn1 = 0.5f * nrm[row+8];
            float2 v;
            v.x = acc[im][jn][0] - hn0; v.y = acc[im][jn][1] - hn0;
            *(float2*)(out + (size_t)row*MM + col) = v;
            if (isK) lmax = fmaxf(lmax, fmaxf(v.x, v.y));
            v.x = acc[im][jn][2] - hn1; v.y = acc[im][jn][3] - hn1;
            *(float2*)(out + (size_t)(row+8)*MM + col) = v;
            if (isK) lmax = fmaxf(lmax, fmaxf(v.x, v.y));
        }
    }
    if (isK) {   // fused global pk max
        #pragma unroll
        for (int o = 16; o; o >>= 1) lmax = fmaxf(lmax, __shfl_xor_sync(0xffffffffu, lmax, o));
        if (lane == 0) wmax[wid] = lmax;
        __syncthreads();
        if (tid == 0) {
            float bm = wmax[0];
            #pragma unroll
            for (int w = 1; w < 8; w++) bm = fmaxf(bm, wmax[w]);
            atomicMaxFloat(&g_gkmax, bm);
        }
    }
}

// ---------------- K3a: phi_q = rnd(exp(pq - rowmax)/16) -----------------------
__global__ __launch_bounds__(256) void k3a() {
    int t = blockIdx.x * 8 + (threadIdx.x >> 5);
    int lane = threadIdx.x & 31;
    float* pq = g_pq + (size_t)t*MM;
    float4 v0 = *(float4*)(pq + lane*4);
    float4 v1 = *(float4*)(pq + 128 + lane*4);
    float mx = fmaxf(fmaxf(fmaxf(v0.x, v0.y), fmaxf(v0.z, v0.w)),
                     fmaxf(fmaxf(v1.x, v1.y), fmaxf(v1.z, v1.w)));
    #pragma unroll
    for (int o = 16; o; o >>= 1) mx = fmaxf(mx, __shfl_xor_sync(0xffffffffu, mx, o));
    float4 e0, e1;
    e0.x = rndtf(expf(v0.x - mx)*0.0625f); e0.y = rndtf(expf(v0.y - mx)*0.0625f);
    e0.z = rndtf(expf(v0.z - mx)*0.0625f); e0.w = rndtf(expf(v0.w - mx)*0.0625f);
    e1.x = rndtf(expf(v1.x - mx)*0.0625f); e1.y = rndtf(expf(v1.y - mx)*0.0625f);
    e1.z = rndtf(expf(v1.z - mx)*0.0625f); e1.w = rndtf(expf(v1.w - mx)*0.0625f);
    *(float4*)(pq + lane*4) = e0;
    *(float4*)(pq + 128 + lane*4) = e1;
}

// ---------------- K3b: phi_k = rnd(exp(pk - gmax)/16) -------------------------
__global__ __launch_bounds__(256) void k3b() {
    float gm = g_gkmax;
    size_t n4 = (size_t)TT*MM/4;
    size_t stride = (size_t)gridDim.x * blockDim.x;
    for (size_t i = (size_t)blockIdx.x*blockDim.x + threadIdx.x; i < n4; i += stride) {
        float4 v = ((float4*)g_pk)[i];
        v.x = rndtf(expf(v.x - gm)*0.0625f); v.y = rndtf(expf(v.y - gm)*0.0625f);
        v.z = rndtf(expf(v.z - gm)*0.0625f); v.w = rndtf(expf(v.w - gm)*0.0625f);
        ((float4*)g_pk)[i] = v;
    }
}

// ---------------- K4: kvT[b][d][m] += sum_s phi_k[s][m] v[s][d] ---------------
__global__ __launch_bounds__(256,2) void k4_mma() {
    extern __shared__ char smarr[];
    uint32_t sb = smem_u32(smarr);
    const int tid = threadIdx.x, lane = tid & 31, wid = tid >> 5;
    const int gid = lane >> 2, tig = lane & 3;
    const int wm = (wid >> 2)*64, wn = (wid & 3)*32;
    const int b = blockIdx.x, m0 = blockIdx.y * 128, sp = blockIdx.z;
    const float* Asrc = g_pk + ((size_t)b*SS + sp*512)*MM + m0;
    const float* Bsrc = g_vr + ((size_t)b*SS + sp*512)*DVV;
    float acc[4][4][4] = {};

    { ldT4(sb, Asrc, MM, tid); ldT4(sb + TILE_B, Bsrc, DVV, tid); CP_COMMIT(); }
    for (int c = 0; c < 16; c++) {
        if (c+1 < 16) {
            uint32_t st = sb + ((c+1)&1)*STG2_B;
            ldT4(st, Asrc + (size_t)(c+1)*32*MM, MM, tid);
            ldT4(st + TILE_B, Bsrc + (size_t)(c+1)*32*DVV, DVV, tid);
            CP_COMMIT();
            CP_WAIT1();
        } else {
            CP_WAIT0();
        }
        __syncthreads();
        const float* S = (const float*)(smarr + (c&1)*STG2_B);
        coreT(S, S + TILE_F, acc, wm, wn, gid, tig);
        __syncthreads();
    }
    float* kvb = g_kvT + (size_t)b*DVV*MM;
    #pragma unroll
    for (int im = 0; im < 4; im++) {
        #pragma unroll
        for (int jn = 0; jn < 4; jn++) {
            int m = m0 + wm + im*16 + gid;
            int d = wn + jn*8 + tig*2;
            atomicAdd(&kvb[(size_t)d*MM + m],       acc[im][jn][0]);
            atomicAdd(&kvb[(size_t)(d+1)*MM + m],   acc[im][jn][1]);
            atomicAdd(&kvb[(size_t)d*MM + m+8],     acc[im][jn][2]);
            atomicAdd(&kvb[(size_t)(d+1)*MM + m+8], acc[im][jn][3]);
        }
    }
}

// ---------------- K4c: round kvT in place -------------------------------------
__global__ __launch_bounds__(256) void k4c_round() {
    int i = blockIdx.x * 256 + threadIdx.x;
    int n = BB*DVV*MM;
    for (; i < n; i += gridDim.x * 256) g_kvT[i] = rndtf(g_kvT[i]);
}

// ---------------- K4b: ksum[b,m] = sum_s phi_k --------------------------------
__global__ __launch_bounds__(256) void k4b_ksum() {
    int b = blockIdx.x, chunk = blockIdx.y, m = threadIdx.x;
    const float* Pk = g_pk + ((size_t)b*SS + chunk*128)*MM + m;
    float s = 0.0f;
    #pragma unroll 8
    for (int i = 0; i < 128; i++) s += Pk[(size_t)i*MM];
    atomicAdd(&g_ksum[b*MM + m], s);
}

// ---------------- K5a: den[t] = dot(phi_q[t], ksum[b]) + eps ------------------
__global__ __launch_bounds__(256) void k5a_den() {
    int t = blockIdx.x * 8 + (threadIdx.x >> 5);
    int lane = threadIdx.x & 31;
    int b = t >> 12;
    const float* pq = g_pq + (size_t)t*MM;
    const float* ks = g_ksum + b*MM;
    float4 p0 = *(const float4*)(pq + lane*4);
    float4 p1 = *(const float4*)(pq + 128 + lane*4);
    float4 k0 = *(const float4*)(ks + lane*4);
    float4 k1 = *(const float4*)(ks + 128 + lane*4);
    float s = p0.x*k0.x + p0.y*k0.y + p0.z*k0.z + p0.w*k0.w
            + p1.x*k1.x + p1.y*k1.y + p1.z*k1.z + p1.w*k1.w;
    #pragma unroll
    for (int o = 16; o; o >>= 1) s += __shfl_xor_sync(0xffffffffu, s, o);
    if (lane == 0) g_den[t] = s + EPSV;
}

// ---------------- K5: out = (phi_q @ kv) / den --------------------------------
__global__ __launch_bounds__(256,2) void k5_mma(float* __restrict__ out) {
    extern __shared__ char smarr[];
    uint32_t sb = smem_u32(smarr);
    const int tid = threadIdx.x, lane = tid & 31, wid = tid >> 5;
    const int gid = lane >> 2, tig = lane & 3;
    const int wm = (wid >> 2)*64, wn = (wid & 3)*32;
    const int row0 = blockIdx.x * 128;
    const int b = blockIdx.x >> 5;
    const float* Asrc = g_pq + (size_t)row0*MM;
    const float* Bsrc = g_kvT + (size_t)b*DVV*MM;
    float acc[4][4][4] = {};

    { ldR4(sb, Asrc, MM, tid); ldR4(sb + TILE_B, Bsrc, MM, tid); CP_COMMIT(); }
    for (int c = 0; c < 8; c++) {
        if (c+1 < 8) {
            uint32_t st = sb + ((c+1)&1)*STG2_B;
            ldR4(st, Asrc + (c+1)*32, MM, tid);
            ldR4(st + TILE_B, Bsrc + (c+1)*32, MM, tid);
            CP_COMMIT();
            CP_WAIT1();
        } else {
            CP_WAIT0();
        }
        __syncthreads();
        const float* S = (const float*)(smarr + (c&1)*STG2_B);
        coreR(S, S + TILE_F, acc, wm, wn, gid, tig);
        __syncthreads();
    }
    #pragma unroll
    for (int im = 0; im < 4; im++) {
        #pragma unroll
        for (int jn = 0; jn < 4; jn++) {
            int row = row0 + wm + im*16 + gid;
            int col = wn + jn*8 + tig*2;
            float inv0 = 1.0f / g_den[row], inv1 = 1.0f / g_den[row+8];
            float2 v;
            v.x = acc[im][jn][0]*inv0; v.y = acc[im][jn][1]*inv0;
            *(float2*)(out + (size_t)row*DVV + col) = v;
            v.x = acc[im][jn][2]*inv1; v.y = acc[im][jn][3]*inv1;
            *(float2*)(out + (size_t)(row+8)*DVV + col) = v;
        }
    }
}

// ---------------- launch ------------------------------------------------------
extern "C" void kernel_launch(void* const* d_in, const int* in_sizes, int n_in,
                              void* d_out, int out_size) {
    const float* x     = (const float*)d_in[0];
    const float* Wq    = (const float*)d_in[1];
    const float* bq    = (const float*)d_in[2];
    const float* Wk    = (const float*)d_in[3];
    const float* bk    = (const float*)d_in[4];
    const float* Wv    = (const float*)d_in[5];
    const float* bv    = (const float*)d_in[6];
    const float* omega = (const float*)d_in[7];
    float* out = (float*)d_out;

    cudaFuncSetAttribute(k1_qk,  cudaFuncAttributeMaxDynamicSharedMemorySize, SMEM_QK);
    cudaFuncSetAttribute(k1_v,   cudaFuncAttributeMaxDynamicSharedMemorySize, SMEM_V);
    cudaFuncSetAttribute(k2_mma, cudaFuncAttributeMaxDynamicSharedMemorySize, SMEM_K2);
    cudaFuncSetAttribute(k4_mma, cudaFuncAttributeMaxDynamicSharedMemorySize, SMEM2);
    cudaFuncSetAttribute(k5_mma, cudaFuncAttributeMaxDynamicSharedMemorySize, SMEM2);

    k_prep_w<<<1536, 256>>>(Wq, Wk, Wv);
    k_prep_om<<<128, 256>>>(omega);
    k0_init<<<64, 256>>>();
    k1_qk<<<256, 256, SMEM_QK>>>(x, bq, bk);
    k1_v<<<256, 256, SMEM_V>>>(x, bv);
    k1b_norms<<<TT/8, 256>>>();
    k2_mma<<<dim3(256, 2, 2), 256, SMEM_K2>>>();
    k3a<<<TT/8, 256>>>();
    k3b<<<2048, 256>>>();
    k4_mma<<<dim3(8, 2, 8), 256, SMEM2>>>();
    k4c_round<<<256, 256>>>();
    k4b_ksum<<<dim3(8, 32), 256>>>();
    k5a_den<<<TT/8, 256>>>();
    k5_mma<<<256, 256, SMEM2>>>(out);
}